// round 1
// baseline (speedup 1.0000x reference)
#include <cuda_runtime.h>
#include <math.h>

#define B_  16
#define T_  2048
#define C_  768
#define H_  64
#define BT_ (B_*T_)

// Scratch (allocation-free rule: device globals)
__device__ float g_K[BT_*H_];
__device__ float g_Q[BT_*H_];
__device__ float g_V[BT_*H_];

// ============================================================================
// QKV projection: [BT, C] x [C, H] for K, Q, V (grid.y selects which).
// BM=128, BN=64, BK=16, 256 threads, 8x4 microtile per thread.
// ============================================================================
#define QKV_BM 128
#define QKV_BK 16
#define AST 132   // padded row stride for A^T tile (floats), 16B-aligned rows
#define BST 68    // padded row stride for B tile

__global__ __launch_bounds__(256, 2)
void qkv_kernel(const float* __restrict__ x, const float* __restrict__ v1,
                const float* __restrict__ Wk, const float* __restrict__ Wq,
                const float* __restrict__ Wv, const float* __restrict__ lamb_p)
{
    __shared__ float Ast[QKV_BK][AST];   // [k][m]
    __shared__ float Bs[QKV_BK][BST];    // [k][n]

    const int tid = threadIdx.x;
    const int gy  = blockIdx.y;                 // 0:K 1:Q 2:V
    const float* __restrict__ W = (gy == 0) ? Wk : (gy == 1) ? Wq : Wv;
    const int row0 = blockIdx.x * QKV_BM;
    const int tx = tid & 15;        // 16 col-groups * 4 cols = 64
    const int ty = tid >> 4;        // 16 row-groups * 8 rows = 128

    float acc[8][4];
    #pragma unroll
    for (int i = 0; i < 8; i++)
        #pragma unroll
        for (int j = 0; j < 4; j++) acc[i][j] = 0.0f;

    for (int k0 = 0; k0 < C_; k0 += QKV_BK) {
        // Load A tile (128x16) as float4, store transposed [k][m]
        #pragma unroll
        for (int it = 0; it < 2; it++) {
            int idx = tid + it * 256;           // 0..511 float4s
            int m  = idx >> 2;
            int kq = idx & 3;
            float4 v = *reinterpret_cast<const float4*>(
                &x[(size_t)(row0 + m) * C_ + k0 + kq * 4]);
            Ast[kq*4 + 0][m] = v.x;
            Ast[kq*4 + 1][m] = v.y;
            Ast[kq*4 + 2][m] = v.z;
            Ast[kq*4 + 3][m] = v.w;
        }
        // Load B tile (16x64) as float4
        {
            int k  = tid >> 4;
            int n4 = tid & 15;
            float4 v = *reinterpret_cast<const float4*>(
                &W[(size_t)(k0 + k) * H_ + n4 * 4]);
            *reinterpret_cast<float4*>(&Bs[k][n4 * 4]) = v;
        }
        __syncthreads();

        #pragma unroll
        for (int kk = 0; kk < QKV_BK; kk++) {
            float4 a0 = *reinterpret_cast<const float4*>(&Ast[kk][ty*8]);
            float4 a1 = *reinterpret_cast<const float4*>(&Ast[kk][ty*8 + 4]);
            float4 b0 = *reinterpret_cast<const float4*>(&Bs[kk][tx*4]);
            float a[8] = {a0.x, a0.y, a0.z, a0.w, a1.x, a1.y, a1.z, a1.w};
            float b[4] = {b0.x, b0.y, b0.z, b0.w};
            #pragma unroll
            for (int i = 0; i < 8; i++)
                #pragma unroll
                for (int j = 0; j < 4; j++)
                    acc[i][j] = fmaf(a[i], b[j], acc[i][j]);
        }
        __syncthreads();
    }

    const float lam = *lamb_p;
    float* __restrict__ dst = (gy == 0) ? g_K : (gy == 1) ? g_Q : g_V;
    #pragma unroll
    for (int i = 0; i < 8; i++) {
        size_t off = (size_t)(row0 + ty*8 + i) * H_ + tx * 4;
        float4 v = make_float4(acc[i][0], acc[i][1], acc[i][2], acc[i][3]);
        if (gy == 2) {
            float4 vv = *reinterpret_cast<const float4*>(&v1[off]);
            v.x = (1.0f - lam) * v.x + lam * vv.x;
            v.y = (1.0f - lam) * v.y + lam * vv.y;
            v.z = (1.0f - lam) * v.z + lam * vv.z;
            v.w = (1.0f - lam) * v.w + lam * vv.w;
        }
        *reinterpret_cast<float4*>(&dst[off]) = v;
    }
}

// ============================================================================
// Flash attention (fp32): 64 queries x 64 keys per tile, online softmax,
// fused output projection. grid = (T/64, B), 256 threads.
// ============================================================================
#define KTS 68                 // padded row stride of transposed K tile
#define ATT_SMEM_FLOATS (64*64 + 64*KTS + 64*64 + 64*64)
#define ATT_SMEM_BYTES  (ATT_SMEM_FLOATS * 4)

__global__ __launch_bounds__(256, 2)
void attn_kernel(const float* __restrict__ Wproj,
                 const float* __restrict__ bproj,
                 float* __restrict__ out)
{
    extern __shared__ float sm[];
    float* Qt = sm;                       // [64][64]  k-major (Qt[k][m])
    float* Kt = Qt + 64*64;               // [64][KTS] k-major (Kt[k][key])
    float* Vs = Kt + 64*KTS;              // [64][64]  row-major (Vs[key][d])
    float* Ps = Vs + 64*64;               // [64][64]  probs / O staging

    const int b   = blockIdx.y;
    const int qt  = gridDim.x - 1 - blockIdx.x;   // heavy tiles first
    const int tid = threadIdx.x;
    const int tx  = tid & 15;
    const int ty  = tid >> 4;
    const size_t base = (size_t)b * T_ * H_;
    const int q0 = qt * 64;

    // Load Q tile transposed (one-time)
    for (int idx = tid; idx < 4096; idx += 256) {
        int k = idx & 63, m = idx >> 6;
        Qt[k*64 + m] = g_Q[base + (size_t)(q0 + m) * H_ + k];
    }

    float mi[4], li[4], o[4][4];
    #pragma unroll
    for (int i = 0; i < 4; i++) {
        mi[i] = -1e30f; li[i] = 0.0f;
        #pragma unroll
        for (int j = 0; j < 4; j++) o[i][j] = 0.0f;
    }

    for (int kt = 0; kt <= qt; kt++) {
        __syncthreads();   // previous PV reads of Vs complete
        // Load K tile transposed + V tile direct
        for (int idx = tid; idx < 4096; idx += 256) {
            int k = idx & 63, key = idx >> 6;
            size_t goff = base + (size_t)(kt*64 + key) * H_ + k;
            Kt[k*KTS + key] = g_K[goff];
            Vs[key*64 + k]  = g_V[goff];
        }
        __syncthreads();

        // S = Q K^T  (4x4 per thread)
        float s[4][4];
        #pragma unroll
        for (int i = 0; i < 4; i++)
            #pragma unroll
            for (int j = 0; j < 4; j++) s[i][j] = 0.0f;

        #pragma unroll 4
        for (int k = 0; k < 64; k++) {
            float4 aq = *reinterpret_cast<const float4*>(&Qt[k*64 + ty*4]);
            float4 bk = *reinterpret_cast<const float4*>(&Kt[k*KTS + tx*4]);
            float a[4] = {aq.x, aq.y, aq.z, aq.w};
            float bb[4] = {bk.x, bk.y, bk.z, bk.w};
            #pragma unroll
            for (int i = 0; i < 4; i++)
                #pragma unroll
                for (int j = 0; j < 4; j++)
                    s[i][j] = fmaf(a[i], bb[j], s[i][j]);
        }

        // scale + causal mask
        const float scale = 0.125f;   // 1/sqrt(64)
        if (kt == qt) {
            #pragma unroll
            for (int i = 0; i < 4; i++) {
                int qrow = q0 + ty*4 + i;
                #pragma unroll
                for (int j = 0; j < 4; j++) {
                    int key = kt*64 + tx*4 + j;
                    s[i][j] = (key <= qrow) ? s[i][j] * scale : -1e30f;
                }
            }
        } else {
            #pragma unroll
            for (int i = 0; i < 4; i++)
                #pragma unroll
                for (int j = 0; j < 4; j++) s[i][j] *= scale;
        }

        // online softmax (row stats across 16-lane tx group)
        #pragma unroll
        for (int i = 0; i < 4; i++) {
            float mx = fmaxf(fmaxf(s[i][0], s[i][1]), fmaxf(s[i][2], s[i][3]));
            #pragma unroll
            for (int d = 1; d < 16; d <<= 1)
                mx = fmaxf(mx, __shfl_xor_sync(0xffffffffu, mx, d));
            float mnew = fmaxf(mi[i], mx);
            float corr = __expf(mi[i] - mnew);
            mi[i] = mnew;
            float rs = 0.0f;
            #pragma unroll
            for (int j = 0; j < 4; j++) {
                float p = __expf(s[i][j] - mnew);
                s[i][j] = p;
                rs += p;
            }
            #pragma unroll
            for (int d = 1; d < 16; d <<= 1)
                rs += __shfl_xor_sync(0xffffffffu, rs, d);
            li[i] = li[i] * corr + rs;
            #pragma unroll
            for (int j = 0; j < 4; j++) o[i][j] *= corr;
        }

        // stage P
        #pragma unroll
        for (int i = 0; i < 4; i++) {
            float4 pv = make_float4(s[i][0], s[i][1], s[i][2], s[i][3]);
            *reinterpret_cast<float4*>(&Ps[(ty*4 + i)*64 + tx*4]) = pv;
        }
        __syncthreads();

        // O += P V
        #pragma unroll 2
        for (int c = 0; c < 64; c++) {
            float4 vv = *reinterpret_cast<const float4*>(&Vs[c*64 + tx*4]);
            float p0 = Ps[(ty*4 + 0)*64 + c];
            float p1 = Ps[(ty*4 + 1)*64 + c];
            float p2 = Ps[(ty*4 + 2)*64 + c];
            float p3 = Ps[(ty*4 + 3)*64 + c];
            o[0][0] = fmaf(p0, vv.x, o[0][0]); o[0][1] = fmaf(p0, vv.y, o[0][1]);
            o[0][2] = fmaf(p0, vv.z, o[0][2]); o[0][3] = fmaf(p0, vv.w, o[0][3]);
            o[1][0] = fmaf(p1, vv.x, o[1][0]); o[1][1] = fmaf(p1, vv.y, o[1][1]);
            o[1][2] = fmaf(p1, vv.z, o[1][2]); o[1][3] = fmaf(p1, vv.w, o[1][3]);
            o[2][0] = fmaf(p2, vv.x, o[2][0]); o[2][1] = fmaf(p2, vv.y, o[2][1]);
            o[2][2] = fmaf(p2, vv.z, o[2][2]); o[2][3] = fmaf(p2, vv.w, o[2][3]);
            o[3][0] = fmaf(p3, vv.x, o[3][0]); o[3][1] = fmaf(p3, vv.y, o[3][1]);
            o[3][2] = fmaf(p3, vv.z, o[3][2]); o[3][3] = fmaf(p3, vv.w, o[3][3]);
        }
    }

    // normalize, stage O, fused projection
    #pragma unroll
    for (int i = 0; i < 4; i++) {
        float inv = 1.0f / li[i];
        #pragma unroll
        for (int j = 0; j < 4; j++) o[i][j] *= inv;
    }
    __syncthreads();
    #pragma unroll
    for (int i = 0; i < 4; i++) {
        float4 ov = make_float4(o[i][0], o[i][1], o[i][2], o[i][3]);
        *reinterpret_cast<float4*>(&Ps[(ty*4 + i)*64 + tx*4]) = ov;
    }
    __syncthreads();

    float r[4][4];
    #pragma unroll
    for (int i = 0; i < 4; i++)
        #pragma unroll
        for (int j = 0; j < 4; j++) r[i][j] = 0.0f;

    #pragma unroll 4
    for (int d = 0; d < 64; d++) {
        float4 w = *reinterpret_cast<const float4*>(&Wproj[d*64 + tx*4]);
        float a0 = Ps[(ty*4 + 0)*64 + d];
        float a1 = Ps[(ty*4 + 1)*64 + d];
        float a2 = Ps[(ty*4 + 2)*64 + d];
        float a3 = Ps[(ty*4 + 3)*64 + d];
        r[0][0] = fmaf(a0, w.x, r[0][0]); r[0][1] = fmaf(a0, w.y, r[0][1]);
        r[0][2] = fmaf(a0, w.z, r[0][2]); r[0][3] = fmaf(a0, w.w, r[0][3]);
        r[1][0] = fmaf(a1, w.x, r[1][0]); r[1][1] = fmaf(a1, w.y, r[1][1]);
        r[1][2] = fmaf(a1, w.z, r[1][2]); r[1][3] = fmaf(a1, w.w, r[1][3]);
        r[2][0] = fmaf(a2, w.x, r[2][0]); r[2][1] = fmaf(a2, w.y, r[2][1]);
        r[2][2] = fmaf(a2, w.z, r[2][2]); r[2][3] = fmaf(a2, w.w, r[2][3]);
        r[3][0] = fmaf(a3, w.x, r[3][0]); r[3][1] = fmaf(a3, w.y, r[3][1]);
        r[3][2] = fmaf(a3, w.z, r[3][2]); r[3][3] = fmaf(a3, w.w, r[3][3]);
    }
    float4 bb = *reinterpret_cast<const float4*>(&bproj[tx*4]);
    #pragma unroll
    for (int i = 0; i < 4; i++) {
        float4 ov = make_float4(r[i][0] + bb.x, r[i][1] + bb.y,
                                r[i][2] + bb.z, r[i][3] + bb.w);
        *reinterpret_cast<float4*>(&out[base + (size_t)(q0 + ty*4 + i) * H_ + tx*4]) = ov;
    }
}

// second tuple output: v1 passthrough
__global__ void copy_v1_kernel(const float* __restrict__ v1, float* __restrict__ dst)
{
    int i = blockIdx.x * blockDim.x + threadIdx.x;
    reinterpret_cast<float4*>(dst)[i] = reinterpret_cast<const float4*>(v1)[i];
}

extern "C" void kernel_launch(void* const* d_in, const int* in_sizes, int n_in,
                              void* d_out, int out_size)
{
    const float* x     = (const float*)d_in[0];
    const float* v1    = (const float*)d_in[1];
    const float* Wk    = (const float*)d_in[2];
    const float* Wq    = (const float*)d_in[3];
    const float* Wv    = (const float*)d_in[4];
    const float* Wproj = (const float*)d_in[5];
    const float* bproj = (const float*)d_in[6];
    const float* lamb  = (const float*)d_in[7];
    float* out = (float*)d_out;

    cudaFuncSetAttribute(attn_kernel,
                         cudaFuncAttributeMaxDynamicSharedMemorySize,
                         ATT_SMEM_BYTES);

    qkv_kernel<<<dim3(BT_ / QKV_BM, 3), 256>>>(x, v1, Wk, Wq, Wv, lamb);
    attn_kernel<<<dim3(T_ / 64, B_), 256, ATT_SMEM_BYTES>>>(Wproj, bproj, out);

    if (out_size >= 2 * BT_ * H_) {
        copy_v1_kernel<<<(BT_ * H_ / 4) / 256, 256>>>(v1, out + (size_t)BT_ * H_);
    }
}

// round 2
// speedup vs baseline: 1.1727x; 1.1727x over previous
#include <cuda_runtime.h>
#include <math.h>

#define B_  16
#define T_  2048
#define C_  768
#define H_  64
#define BT_ (B_*T_)

// Scratch (allocation-free rule: device globals)
__device__ float g_K[BT_*H_];
__device__ float g_Q[BT_*H_];
__device__ float g_V[BT_*H_];

// ---------------------------------------------------------------------------
// packed fp32x2 FMA (exact fp32 math, 2x issue density; ptxas never auto-emits)
// ---------------------------------------------------------------------------
union F2U { float2 f; unsigned long long u; };

__device__ __forceinline__ float2 ffma2(float2 a, float2 b, float2 c) {
    F2U A, Bv, C, D;
    A.f = a; Bv.f = b; C.f = c;
    asm("fma.rn.f32x2 %0, %1, %2, %3;"
        : "=l"(D.u) : "l"(A.u), "l"(Bv.u), "l"(C.u));
    return D.f;
}
__device__ __forceinline__ float2 dup2(float a) { return make_float2(a, a); }

// ============================================================================
// Fused QKV projection: one pass over x computes K|Q|V (192 output cols).
// BM=64 rows, 128 threads, microtile 8 rows x 12 cols (4 per matrix).
// ============================================================================
#define QBM 64
#define QBK 16
#define AST 68
#define BST 200

__global__ __launch_bounds__(128, 3)
void qkv_kernel(const float* __restrict__ x, const float* __restrict__ v1,
                const float* __restrict__ Wk, const float* __restrict__ Wq,
                const float* __restrict__ Wv, const float* __restrict__ lamb_p)
{
    __shared__ float Ast[QBK][AST];   // [k][m]
    __shared__ float Bs[QBK][BST];    // [k][n]  n = 3*64

    const int tid = threadIdx.x;
    const int row0 = blockIdx.x * QBM;
    const int tx = tid & 15;     // 16 col-groups (4 cols per matrix)
    const int ty = tid >> 4;     // 8 row-groups * 8 rows = 64

    const float* Wm[3] = {Wk, Wq, Wv};

    float2 acc[8][3][2];
    #pragma unroll
    for (int i = 0; i < 8; i++)
        #pragma unroll
        for (int m = 0; m < 3; m++) {
            acc[i][m][0] = make_float2(0.f, 0.f);
            acc[i][m][1] = make_float2(0.f, 0.f);
        }

    for (int k0 = 0; k0 < C_; k0 += QBK) {
        // A tile (64x16) -> transposed [k][m]
        #pragma unroll
        for (int it = 0; it < 2; it++) {
            int idx = tid + it * 128;          // 0..255 float4s
            int m  = idx >> 2;
            int kq = idx & 3;
            float4 v = *reinterpret_cast<const float4*>(
                &x[(size_t)(row0 + m) * C_ + k0 + kq * 4]);
            Ast[kq*4 + 0][m] = v.x;
            Ast[kq*4 + 1][m] = v.y;
            Ast[kq*4 + 2][m] = v.z;
            Ast[kq*4 + 3][m] = v.w;
        }
        // B tile (16 x 192)
        #pragma unroll
        for (int it = 0; it < 6; it++) {
            int idx = tid + it * 128;          // 0..767 float4s
            int k   = idx / 48;
            int c4  = idx % 48;
            int wm  = c4 >> 4;
            int col = (c4 & 15) * 4;
            float4 v = *reinterpret_cast<const float4*>(
                &Wm[wm][(size_t)(k0 + k) * H_ + col]);
            *reinterpret_cast<float4*>(&Bs[k][wm*64 + col]) = v;
        }
        __syncthreads();

        #pragma unroll
        for (int kk = 0; kk < QBK; kk++) {
            float4 a0 = *reinterpret_cast<const float4*>(&Ast[kk][ty*8]);
            float4 a1 = *reinterpret_cast<const float4*>(&Ast[kk][ty*8 + 4]);
            float a[8] = {a0.x, a0.y, a0.z, a0.w, a1.x, a1.y, a1.z, a1.w};
            float2 b[3][2];
            #pragma unroll
            for (int m = 0; m < 3; m++) {
                float4 bv = *reinterpret_cast<const float4*>(&Bs[kk][m*64 + tx*4]);
                b[m][0] = make_float2(bv.x, bv.y);
                b[m][1] = make_float2(bv.z, bv.w);
            }
            #pragma unroll
            for (int i = 0; i < 8; i++) {
                float2 ad = dup2(a[i]);
                #pragma unroll
                for (int m = 0; m < 3; m++) {
                    acc[i][m][0] = ffma2(ad, b[m][0], acc[i][m][0]);
                    acc[i][m][1] = ffma2(ad, b[m][1], acc[i][m][1]);
                }
            }
        }
        __syncthreads();
    }

    const float lam = *lamb_p;
    float* dsts[3] = {g_K, g_Q, g_V};
    #pragma unroll
    for (int m = 0; m < 3; m++) {
        float* __restrict__ dst = dsts[m];
        #pragma unroll
        for (int i = 0; i < 8; i++) {
            size_t off = (size_t)(row0 + ty*8 + i) * H_ + tx * 4;
            float4 v = make_float4(acc[i][m][0].x, acc[i][m][0].y,
                                   acc[i][m][1].x, acc[i][m][1].y);
            if (m == 2) {
                float4 vv = *reinterpret_cast<const float4*>(&v1[off]);
                v.x = (1.0f - lam) * v.x + lam * vv.x;
                v.y = (1.0f - lam) * v.y + lam * vv.y;
                v.z = (1.0f - lam) * v.z + lam * vv.z;
                v.w = (1.0f - lam) * v.w + lam * vv.w;
            }
            *reinterpret_cast<float4*>(&dst[off]) = v;
        }
    }
}

// ============================================================================
// Flash attention: 128q x 128k tiles, 256 threads, 8x8 microtile S-gemm,
// packed fp32x2 FMAs, transposed P staging (bank-swizzled rows), fused Wproj.
// ============================================================================
#define QTS 136   // Qt/Kt row stride (floats)
#define VTS 68    // V row stride
#define PTS 132   // Pst row stride
#define ATT_SMEM_FLOATS (64*QTS + 64*QTS + 128*VTS + 128*PTS)
#define ATT_SMEM_BYTES  (ATT_SMEM_FLOATS * 4)

// scalar pick from float2-pair array (compile-time j)
#define SVAL(arr, i, j) (((j) & 1) ? arr[i][(j) >> 1].y : arr[i][(j) >> 1].x)

__global__ __launch_bounds__(256, 1)
void attn_kernel(const float* __restrict__ Wproj,
                 const float* __restrict__ bproj,
                 float* __restrict__ out)
{
    extern __shared__ float sm[];
    float* Qt  = sm;                 // [64][QTS]  Qt[d][q]
    float* Kt  = Qt + 64*QTS;        // [64][QTS]  Kt[d][key]
    float* Vs  = Kt + 64*QTS;        // [128][VTS] Vs[key][d]
    float* Pst = Vs + 128*VTS;       // [128][PTS] P^T, swizzled rows; reused as O^T

    const int bid = blockIdx.x;
    const int b   = bid & 15;
    const int qt  = 15 - (bid >> 4);          // heavy tiles scheduled first
    const int tid = threadIdx.x;
    const int tx  = tid & 15;
    const int ty  = tid >> 4;
    const size_t base = (size_t)b * T_ * H_;
    const int q0 = qt * 128;

    // Load Q tile transposed: Qt[d][q]
    #pragma unroll
    for (int it = 0; it < 8; it++) {
        int idx = tid + it * 256;
        int q = idx & 127, d4 = idx >> 7;
        float4 g = *reinterpret_cast<const float4*>(
            &g_Q[base + (size_t)(q0 + q) * H_ + d4*4]);
        Qt[(d4*4+0)*QTS + q] = g.x;
        Qt[(d4*4+1)*QTS + q] = g.y;
        Qt[(d4*4+2)*QTS + q] = g.z;
        Qt[(d4*4+3)*QTS + q] = g.w;
    }

    float2 o2[8][2];
    float mi[8], li[8];
    #pragma unroll
    for (int i = 0; i < 8; i++) {
        mi[i] = -1e30f; li[i] = 0.0f;
        o2[i][0] = make_float2(0.f, 0.f);
        o2[i][1] = make_float2(0.f, 0.f);
    }

    for (int kb = 0; kb <= qt; kb++) {
        __syncthreads();
        // K tile transposed Kt[d][key]; V tile direct
        #pragma unroll
        for (int it = 0; it < 8; it++) {
            int idx = tid + it * 256;
            int key = idx & 127, d4 = idx >> 7;
            float4 g = *reinterpret_cast<const float4*>(
                &g_K[base + (size_t)(kb*128 + key) * H_ + d4*4]);
            Kt[(d4*4+0)*QTS + key] = g.x;
            Kt[(d4*4+1)*QTS + key] = g.y;
            Kt[(d4*4+2)*QTS + key] = g.z;
            Kt[(d4*4+3)*QTS + key] = g.w;
        }
        #pragma unroll
        for (int it = 0; it < 8; it++) {
            int idx = tid + it * 256;
            int key = idx >> 4, d4 = idx & 15;
            float4 g = *reinterpret_cast<const float4*>(
                &g_V[base + (size_t)(kb*128 + key) * H_ + d4*4]);
            *reinterpret_cast<float4*>(&Vs[key*VTS + d4*4]) = g;
        }
        __syncthreads();

        // S = Q K^T : 8x8 per thread (rows ty*8.., keys tx*8..)
        float2 s2[8][4];
        #pragma unroll
        for (int i = 0; i < 8; i++)
            #pragma unroll
            for (int jp = 0; jp < 4; jp++) s2[i][jp] = make_float2(0.f, 0.f);

        #pragma unroll 2
        for (int k = 0; k < 64; k++) {
            float4 a0 = *reinterpret_cast<const float4*>(&Qt[k*QTS + ty*8]);
            float4 a1 = *reinterpret_cast<const float4*>(&Qt[k*QTS + ty*8 + 4]);
            float4 b0 = *reinterpret_cast<const float4*>(&Kt[k*QTS + tx*8]);
            float4 b1 = *reinterpret_cast<const float4*>(&Kt[k*QTS + tx*8 + 4]);
            float a[8] = {a0.x, a0.y, a0.z, a0.w, a1.x, a1.y, a1.z, a1.w};
            float2 bb[4] = {make_float2(b0.x, b0.y), make_float2(b0.z, b0.w),
                            make_float2(b1.x, b1.y), make_float2(b1.z, b1.w)};
            #pragma unroll
            for (int i = 0; i < 8; i++) {
                float2 ad = dup2(a[i]);
                #pragma unroll
                for (int jp = 0; jp < 4; jp++)
                    s2[i][jp] = ffma2(ad, bb[jp], s2[i][jp]);
            }
        }

        // scale + causal mask (diagonal block only)
        const float scale = 0.125f;
        if (kb == qt) {
            #pragma unroll
            for (int i = 0; i < 8; i++) {
                int qrow = ty*8 + i;           // local (same tile offset)
                #pragma unroll
                for (int jj = 0; jj < 8; jj++) {
                    int key = tx*8 + jj;
                    float v = SVAL(s2, i, jj) * scale;
                    v = (key <= qrow) ? v : -1e30f;
                    if (jj & 1) s2[i][jj>>1].y = v; else s2[i][jj>>1].x = v;
                }
            }
        } else {
            #pragma unroll
            for (int i = 0; i < 8; i++)
                #pragma unroll
                for (int jp = 0; jp < 4; jp++) {
                    s2[i][jp].x *= scale; s2[i][jp].y *= scale;
                }
        }

        // online softmax per row (reduce across 16 tx lanes)
        #pragma unroll
        for (int i = 0; i < 8; i++) {
            float mx = -1e30f;
            #pragma unroll
            for (int jp = 0; jp < 4; jp++)
                mx = fmaxf(mx, fmaxf(s2[i][jp].x, s2[i][jp].y));
            #pragma unroll
            for (int d = 1; d < 16; d <<= 1)
                mx = fmaxf(mx, __shfl_xor_sync(0xffffffffu, mx, d));
            float mnew = fmaxf(mi[i], mx);
            float corr = __expf(mi[i] - mnew);
            mi[i] = mnew;
            float rs = 0.0f;
            #pragma unroll
            for (int jp = 0; jp < 4; jp++) {
                float px = __expf(s2[i][jp].x - mnew);
                float py = __expf(s2[i][jp].y - mnew);
                s2[i][jp].x = px; s2[i][jp].y = py;
                rs += px + py;
            }
            #pragma unroll
            for (int d = 1; d < 16; d <<= 1)
                rs += __shfl_xor_sync(0xffffffffu, rs, d);
            li[i] = li[i] * corr + rs;
            o2[i][0].x *= corr; o2[i][0].y *= corr;
            o2[i][1].x *= corr; o2[i][1].y *= corr;
        }

        // stage P transposed: logical key = tx*8+jj stored at phys row jj*16+tx
        #pragma unroll
        for (int jj = 0; jj < 8; jj++) {
            float4 lo = make_float4(SVAL(s2,0,jj), SVAL(s2,1,jj),
                                    SVAL(s2,2,jj), SVAL(s2,3,jj));
            float4 hi = make_float4(SVAL(s2,4,jj), SVAL(s2,5,jj),
                                    SVAL(s2,6,jj), SVAL(s2,7,jj));
            int pr = jj*16 + tx;
            *reinterpret_cast<float4*>(&Pst[pr*PTS + ty*8])     = lo;
            *reinterpret_cast<float4*>(&Pst[pr*PTS + ty*8 + 4]) = hi;
        }
        __syncthreads();

        // O += P V  (rows ty*8.., d cols tx*4..)
        #pragma unroll 4
        for (int c = 0; c < 128; c++) {
            int pr = ((c & 7) << 4) | (c >> 3);     // physical row of logical key c
            float4 p0 = *reinterpret_cast<const float4*>(&Pst[pr*PTS + ty*8]);
            float4 p1 = *reinterpret_cast<const float4*>(&Pst[pr*PTS + ty*8 + 4]);
            float4 vv = *reinterpret_cast<const float4*>(&Vs[c*VTS + tx*4]);
            float2 v01 = make_float2(vv.x, vv.y);
            float2 v23 = make_float2(vv.z, vv.w);
            float p[8] = {p0.x, p0.y, p0.z, p0.w, p1.x, p1.y, p1.z, p1.w};
            #pragma unroll
            for (int i = 0; i < 8; i++) {
                float2 pd = dup2(p[i]);
                o2[i][0] = ffma2(pd, v01, o2[i][0]);
                o2[i][1] = ffma2(pd, v23, o2[i][1]);
            }
        }
    }

    // normalize
    #pragma unroll
    for (int i = 0; i < 8; i++) {
        float inv = 1.0f / li[i];
        o2[i][0].x *= inv; o2[i][0].y *= inv;
        o2[i][1].x *= inv; o2[i][1].y *= inv;
    }

    // stage O transposed into Pst: logical d = tx*4+j at phys row j*16+tx
    __syncthreads();
    #pragma unroll
    for (int j = 0; j < 4; j++) {
        float4 lo = make_float4(SVAL(o2,0,j), SVAL(o2,1,j),
                                SVAL(o2,2,j), SVAL(o2,3,j));
        float4 hi = make_float4(SVAL(o2,4,j), SVAL(o2,5,j),
                                SVAL(o2,6,j), SVAL(o2,7,j));
        int pr = j*16 + tx;
        *reinterpret_cast<float4*>(&Pst[pr*PTS + ty*8])     = lo;
        *reinterpret_cast<float4*>(&Pst[pr*PTS + ty*8 + 4]) = hi;
    }
    __syncthreads();

    // fused projection: rows ty*8.., out cols tx*4..
    float2 r2[8][2];
    #pragma unroll
    for (int i = 0; i < 8; i++) {
        r2[i][0] = make_float2(0.f, 0.f);
        r2[i][1] = make_float2(0.f, 0.f);
    }
    #pragma unroll 4
    for (int d = 0; d < 64; d++) {
        int pr = ((d & 3) << 4) | (d >> 2);
        float4 a0 = *reinterpret_cast<const float4*>(&Pst[pr*PTS + ty*8]);
        float4 a1 = *reinterpret_cast<const float4*>(&Pst[pr*PTS + ty*8 + 4]);
        float4 w  = *reinterpret_cast<const float4*>(&Wproj[d*64 + tx*4]);
        float2 w01 = make_float2(w.x, w.y);
        float2 w23 = make_float2(w.z, w.w);
        float a[8] = {a0.x, a0.y, a0.z, a0.w, a1.x, a1.y, a1.z, a1.w};
        #pragma unroll
        for (int i = 0; i < 8; i++) {
            float2 ad = dup2(a[i]);
            r2[i][0] = ffma2(ad, w01, r2[i][0]);
            r2[i][1] = ffma2(ad, w23, r2[i][1]);
        }
    }
    float4 bb = *reinterpret_cast<const float4*>(&bproj[tx*4]);
    #pragma unroll
    for (int i = 0; i < 8; i++) {
        float4 ov = make_float4(r2[i][0].x + bb.x, r2[i][0].y + bb.y,
                                r2[i][1].x + bb.z, r2[i][1].y + bb.w);
        *reinterpret_cast<float4*>(
            &out[base + (size_t)(q0 + ty*8 + i) * H_ + tx*4]) = ov;
    }
}

// second tuple output: v1 passthrough
__global__ void copy_v1_kernel(const float* __restrict__ v1, float* __restrict__ dst)
{
    int i = blockIdx.x * blockDim.x + threadIdx.x;
    reinterpret_cast<float4*>(dst)[i] = reinterpret_cast<const float4*>(v1)[i];
}

extern "C" void kernel_launch(void* const* d_in, const int* in_sizes, int n_in,
                              void* d_out, int out_size)
{
    const float* x     = (const float*)d_in[0];
    const float* v1    = (const float*)d_in[1];
    const float* Wk    = (const float*)d_in[2];
    const float* Wq    = (const float*)d_in[3];
    const float* Wv    = (const float*)d_in[4];
    const float* Wproj = (const float*)d_in[5];
    const float* bproj = (const float*)d_in[6];
    const float* lamb  = (const float*)d_in[7];
    float* out = (float*)d_out;

    cudaFuncSetAttribute(attn_kernel,
                         cudaFuncAttributeMaxDynamicSharedMemorySize,
                         ATT_SMEM_BYTES);

    qkv_kernel<<<BT_ / QBM, 128>>>(x, v1, Wk, Wq, Wv, lamb);
    attn_kernel<<<16 * B_, 256, ATT_SMEM_BYTES>>>(Wproj, bproj, out);

    if (out_size >= 2 * BT_ * H_) {
        copy_v1_kernel<<<(BT_ * H_ / 4) / 256, 256>>>(v1, out + (size_t)BT_ * H_);
    }
}

// round 3
// speedup vs baseline: 1.6268x; 1.3873x over previous
#include <cuda_runtime.h>
#include <math.h>

#define B_  16
#define T_  2048
#define C_  768
#define H_  64
#define BT_ (B_*T_)

// Scratch (allocation-free rule: device globals)
__device__ float g_K[BT_*H_];
__device__ float g_Q[BT_*H_];
__device__ float g_V[BT_*H_];

// ---------------------------------------------------------------------------
// packed fp32x2 FMA (exact fp32 math, 2x issue density; ptxas never auto-emits)
// ---------------------------------------------------------------------------
union F2U { float2 f; unsigned long long u; };

__device__ __forceinline__ float2 ffma2(float2 a, float2 b, float2 c) {
    F2U A, Bv, C, D;
    A.f = a; Bv.f = b; C.f = c;
    asm("fma.rn.f32x2 %0, %1, %2, %3;"
        : "=l"(D.u) : "l"(A.u), "l"(Bv.u), "l"(C.u));
    return D.f;
}
__device__ __forceinline__ float2 dup2(float a) { return make_float2(a, a); }

// ============================================================================
// Fused QKV projection, double-buffered, warp-broadcast A.
// BM=64 rows, BN=192 (K|Q|V), BK=16, 256 threads (8 warps).
// Warp w owns rows w*8..w*8+7 (A fragment is a full-warp broadcast LDS).
// Lane l owns cols {2l, 2l+1} of each of K, Q, V.
// Microtile 8 rows x (2 cols x 3 mats) = 24 FFMA2 per k-step per thread.
// ============================================================================
#define QBM 64
#define QBK 16
#define AST 72    // Ast row stride (16B aligned: 288B)
#define BST 200   // Bs row stride (16B aligned: 800B)

__global__ __launch_bounds__(256, 2)
void qkv_kernel(const float* __restrict__ x, const float* __restrict__ v1,
                const float* __restrict__ Wk, const float* __restrict__ Wq,
                const float* __restrict__ Wv, const float* __restrict__ lamb_p)
{
    __shared__ float Ast[2][QBK][AST];   // [buf][k][m]
    __shared__ float Bs[2][QBK][BST];    // [buf][k][n], n = 3*64

    const int tid  = threadIdx.x;
    const int warp = tid >> 5;        // 8 warps -> row groups of 8
    const int lane = tid & 31;        // 32 lanes -> col pairs
    const int row0 = blockIdx.x * QBM;

    const float* Wm[3] = {Wk, Wq, Wv};

    // global-load indices (fixed per thread)
    const int arow = tid >> 2;        // 0..63
    const int ak4  = tid & 3;         // 0..3  (float4 within 16-float k-range)

    float4 pa;          // A prefetch
    float4 pb[3];       // B prefetch
    int bk[3], bcol[3]; // B smem coords
    #pragma unroll
    for (int it = 0; it < 3; it++) {
        int idx = tid + it * 256;     // 0..767
        bk[it]  = idx / 48;
        int c4  = idx % 48;
        int wm  = c4 >> 4;
        int col = (c4 & 15) * 4;
        bcol[it] = wm * 64 + col;
    }

    auto load_global = [&](int k0) {
        pa = *reinterpret_cast<const float4*>(
            &x[(size_t)(row0 + arow) * C_ + k0 + ak4 * 4]);
        #pragma unroll
        for (int it = 0; it < 3; it++) {
            int idx = tid + it * 256;
            int c4  = idx % 48;
            int wm  = c4 >> 4;
            int col = (c4 & 15) * 4;
            pb[it] = *reinterpret_cast<const float4*>(
                &Wm[wm][(size_t)(k0 + bk[it]) * H_ + col]);
        }
    };
    auto store_smem = [&](int buf) {
        Ast[buf][ak4*4 + 0][arow] = pa.x;
        Ast[buf][ak4*4 + 1][arow] = pa.y;
        Ast[buf][ak4*4 + 2][arow] = pa.z;
        Ast[buf][ak4*4 + 3][arow] = pa.w;
        #pragma unroll
        for (int it = 0; it < 3; it++)
            *reinterpret_cast<float4*>(&Bs[buf][bk[it]][bcol[it]]) = pb[it];
    };

    load_global(0);
    store_smem(0);
    __syncthreads();

    float2 acc[8][3];
    #pragma unroll
    for (int i = 0; i < 8; i++)
        #pragma unroll
        for (int m = 0; m < 3; m++) acc[i][m] = make_float2(0.f, 0.f);

    const int NK = C_ / QBK;   // 48
    for (int t = 0; t < NK; t++) {
        const int cur = t & 1;
        if (t + 1 < NK) load_global((t + 1) * QBK);   // overlap with compute

        #pragma unroll
        for (int kk = 0; kk < QBK; kk++) {
            // A fragment: rows warp*8..+7 — full-warp broadcast
            float4 a0 = *reinterpret_cast<const float4*>(&Ast[cur][kk][warp*8]);
            float4 a1 = *reinterpret_cast<const float4*>(&Ast[cur][kk][warp*8 + 4]);
            // B fragment: one float2 per matrix, contiguous across lanes
            float2 b0 = *reinterpret_cast<const float2*>(&Bs[cur][kk][0*64  + lane*2]);
            float2 b1 = *reinterpret_cast<const float2*>(&Bs[cur][kk][1*64  + lane*2]);
            float2 b2 = *reinterpret_cast<const float2*>(&Bs[cur][kk][2*64  + lane*2]);
            float a[8] = {a0.x, a0.y, a0.z, a0.w, a1.x, a1.y, a1.z, a1.w};
            #pragma unroll
            for (int i = 0; i < 8; i++) {
                float2 ad = dup2(a[i]);
                acc[i][0] = ffma2(ad, b0, acc[i][0]);
                acc[i][1] = ffma2(ad, b1, acc[i][1]);
                acc[i][2] = ffma2(ad, b2, acc[i][2]);
            }
        }
        __syncthreads();
        if (t + 1 < NK) {
            store_smem((t + 1) & 1);
            __syncthreads();
        }
    }

    const float lam = *lamb_p;
    float* dsts[3] = {g_K, g_Q, g_V};
    #pragma unroll
    for (int m = 0; m < 3; m++) {
        float* __restrict__ dst = dsts[m];
        #pragma unroll
        for (int i = 0; i < 8; i++) {
            size_t off = (size_t)(row0 + warp*8 + i) * H_ + lane * 2;
            float2 v = acc[i][m];
            if (m == 2) {
                float2 vv = *reinterpret_cast<const float2*>(&v1[off]);
                v.x = (1.0f - lam) * v.x + lam * vv.x;
                v.y = (1.0f - lam) * v.y + lam * vv.y;
            }
            *reinterpret_cast<float2*>(&dst[off]) = v;
        }
    }
}

// ============================================================================
// Flash attention: 128q x 128k tiles, 256 threads, 8x8 microtile S-gemm,
// packed fp32x2 FMAs, transposed P staging (bank-swizzled rows), fused Wproj.
// (unchanged from R2 — measured ~222us)
// ============================================================================
#define QTS 136   // Qt/Kt row stride (floats)
#define VTS 68    // V row stride
#define PTS 132   // Pst row stride
#define ATT_SMEM_FLOATS (64*QTS + 64*QTS + 128*VTS + 128*PTS)
#define ATT_SMEM_BYTES  (ATT_SMEM_FLOATS * 4)

#define SVAL(arr, i, j) (((j) & 1) ? arr[i][(j) >> 1].y : arr[i][(j) >> 1].x)

__global__ __launch_bounds__(256, 1)
void attn_kernel(const float* __restrict__ Wproj,
                 const float* __restrict__ bproj,
                 float* __restrict__ out)
{
    extern __shared__ float sm[];
    float* Qt  = sm;                 // [64][QTS]  Qt[d][q]
    float* Kt  = Qt + 64*QTS;        // [64][QTS]  Kt[d][key]
    float* Vs  = Kt + 64*QTS;        // [128][VTS] Vs[key][d]
    float* Pst = Vs + 128*VTS;       // [128][PTS] P^T swizzled; reused as O^T

    const int bid = blockIdx.x;
    const int b   = bid & 15;
    const int qt  = 15 - (bid >> 4);          // heavy tiles first
    const int tid = threadIdx.x;
    const int tx  = tid & 15;
    const int ty  = tid >> 4;
    const size_t base = (size_t)b * T_ * H_;
    const int q0 = qt * 128;

    #pragma unroll
    for (int it = 0; it < 8; it++) {
        int idx = tid + it * 256;
        int q = idx & 127, d4 = idx >> 7;
        float4 g = *reinterpret_cast<const float4*>(
            &g_Q[base + (size_t)(q0 + q) * H_ + d4*4]);
        Qt[(d4*4+0)*QTS + q] = g.x;
        Qt[(d4*4+1)*QTS + q] = g.y;
        Qt[(d4*4+2)*QTS + q] = g.z;
        Qt[(d4*4+3)*QTS + q] = g.w;
    }

    float2 o2[8][2];
    float mi[8], li[8];
    #pragma unroll
    for (int i = 0; i < 8; i++) {
        mi[i] = -1e30f; li[i] = 0.0f;
        o2[i][0] = make_float2(0.f, 0.f);
        o2[i][1] = make_float2(0.f, 0.f);
    }

    for (int kb = 0; kb <= qt; kb++) {
        __syncthreads();
        #pragma unroll
        for (int it = 0; it < 8; it++) {
            int idx = tid + it * 256;
            int key = idx & 127, d4 = idx >> 7;
            float4 g = *reinterpret_cast<const float4*>(
                &g_K[base + (size_t)(kb*128 + key) * H_ + d4*4]);
            Kt[(d4*4+0)*QTS + key] = g.x;
            Kt[(d4*4+1)*QTS + key] = g.y;
            Kt[(d4*4+2)*QTS + key] = g.z;
            Kt[(d4*4+3)*QTS + key] = g.w;
        }
        #pragma unroll
        for (int it = 0; it < 8; it++) {
            int idx = tid + it * 256;
            int key = idx >> 4, d4 = idx & 15;
            float4 g = *reinterpret_cast<const float4*>(
                &g_V[base + (size_t)(kb*128 + key) * H_ + d4*4]);
            *reinterpret_cast<float4*>(&Vs[key*VTS + d4*4]) = g;
        }
        __syncthreads();

        float2 s2[8][4];
        #pragma unroll
        for (int i = 0; i < 8; i++)
            #pragma unroll
            for (int jp = 0; jp < 4; jp++) s2[i][jp] = make_float2(0.f, 0.f);

        #pragma unroll 2
        for (int k = 0; k < 64; k++) {
            float4 a0 = *reinterpret_cast<const float4*>(&Qt[k*QTS + ty*8]);
            float4 a1 = *reinterpret_cast<const float4*>(&Qt[k*QTS + ty*8 + 4]);
            float4 b0 = *reinterpret_cast<const float4*>(&Kt[k*QTS + tx*8]);
            float4 b1 = *reinterpret_cast<const float4*>(&Kt[k*QTS + tx*8 + 4]);
            float a[8] = {a0.x, a0.y, a0.z, a0.w, a1.x, a1.y, a1.z, a1.w};
            float2 bb[4] = {make_float2(b0.x, b0.y), make_float2(b0.z, b0.w),
                            make_float2(b1.x, b1.y), make_float2(b1.z, b1.w)};
            #pragma unroll
            for (int i = 0; i < 8; i++) {
                float2 ad = dup2(a[i]);
                #pragma unroll
                for (int jp = 0; jp < 4; jp++)
                    s2[i][jp] = ffma2(ad, bb[jp], s2[i][jp]);
            }
        }

        const float scale = 0.125f;
        if (kb == qt) {
            #pragma unroll
            for (int i = 0; i < 8; i++) {
                int qrow = ty*8 + i;
                #pragma unroll
                for (int jj = 0; jj < 8; jj++) {
                    int key = tx*8 + jj;
                    float v = SVAL(s2, i, jj) * scale;
                    v = (key <= qrow) ? v : -1e30f;
                    if (jj & 1) s2[i][jj>>1].y = v; else s2[i][jj>>1].x = v;
                }
            }
        } else {
            #pragma unroll
            for (int i = 0; i < 8; i++)
                #pragma unroll
                for (int jp = 0; jp < 4; jp++) {
                    s2[i][jp].x *= scale; s2[i][jp].y *= scale;
                }
        }

        #pragma unroll
        for (int i = 0; i < 8; i++) {
            float mx = -1e30f;
            #pragma unroll
            for (int jp = 0; jp < 4; jp++)
                mx = fmaxf(mx, fmaxf(s2[i][jp].x, s2[i][jp].y));
            #pragma unroll
            for (int d = 1; d < 16; d <<= 1)
                mx = fmaxf(mx, __shfl_xor_sync(0xffffffffu, mx, d));
            float mnew = fmaxf(mi[i], mx);
            float corr = __expf(mi[i] - mnew);
            mi[i] = mnew;
            float rs = 0.0f;
            #pragma unroll
            for (int jp = 0; jp < 4; jp++) {
                float px = __expf(s2[i][jp].x - mnew);
                float py = __expf(s2[i][jp].y - mnew);
                s2[i][jp].x = px; s2[i][jp].y = py;
                rs += px + py;
            }
            #pragma unroll
            for (int d = 1; d < 16; d <<= 1)
                rs += __shfl_xor_sync(0xffffffffu, rs, d);
            li[i] = li[i] * corr + rs;
            o2[i][0].x *= corr; o2[i][0].y *= corr;
            o2[i][1].x *= corr; o2[i][1].y *= corr;
        }

        #pragma unroll
        for (int jj = 0; jj < 8; jj++) {
            float4 lo = make_float4(SVAL(s2,0,jj), SVAL(s2,1,jj),
                                    SVAL(s2,2,jj), SVAL(s2,3,jj));
            float4 hi = make_float4(SVAL(s2,4,jj), SVAL(s2,5,jj),
                                    SVAL(s2,6,jj), SVAL(s2,7,jj));
            int pr = jj*16 + tx;
            *reinterpret_cast<float4*>(&Pst[pr*PTS + ty*8])     = lo;
            *reinterpret_cast<float4*>(&Pst[pr*PTS + ty*8 + 4]) = hi;
        }
        __syncthreads();

        #pragma unroll 4
        for (int c = 0; c < 128; c++) {
            int pr = ((c & 7) << 4) | (c >> 3);
            float4 p0 = *reinterpret_cast<const float4*>(&Pst[pr*PTS + ty*8]);
            float4 p1 = *reinterpret_cast<const float4*>(&Pst[pr*PTS + ty*8 + 4]);
            float4 vv = *reinterpret_cast<const float4*>(&Vs[c*VTS + tx*4]);
            float2 v01 = make_float2(vv.x, vv.y);
            float2 v23 = make_float2(vv.z, vv.w);
            float p[8] = {p0.x, p0.y, p0.z, p0.w, p1.x, p1.y, p1.z, p1.w};
            #pragma unroll
            for (int i = 0; i < 8; i++) {
                float2 pd = dup2(p[i]);
                o2[i][0] = ffma2(pd, v01, o2[i][0]);
                o2[i][1] = ffma2(pd, v23, o2[i][1]);
            }
        }
    }

    #pragma unroll
    for (int i = 0; i < 8; i++) {
        float inv = 1.0f / li[i];
        o2[i][0].x *= inv; o2[i][0].y *= inv;
        o2[i][1].x *= inv; o2[i][1].y *= inv;
    }

    __syncthreads();
    #pragma unroll
    for (int j = 0; j < 4; j++) {
        float4 lo = make_float4(SVAL(o2,0,j), SVAL(o2,1,j),
                                SVAL(o2,2,j), SVAL(o2,3,j));
        float4 hi = make_float4(SVAL(o2,4,j), SVAL(o2,5,j),
                                SVAL(o2,6,j), SVAL(o2,7,j));
        int pr = j*16 + tx;
        *reinterpret_cast<float4*>(&Pst[pr*PTS + ty*8])     = lo;
        *reinterpret_cast<float4*>(&Pst[pr*PTS + ty*8 + 4]) = hi;
    }
    __syncthreads();

    float2 r2[8][2];
    #pragma unroll
    for (int i = 0; i < 8; i++) {
        r2[i][0] = make_float2(0.f, 0.f);
        r2[i][1] = make_float2(0.f, 0.f);
    }
    #pragma unroll 4
    for (int d = 0; d < 64; d++) {
        int pr = ((d & 3) << 4) | (d >> 2);
        float4 a0 = *reinterpret_cast<const float4*>(&Pst[pr*PTS + ty*8]);
        float4 a1 = *reinterpret_cast<const float4*>(&Pst[pr*PTS + ty*8 + 4]);
        float4 w  = *reinterpret_cast<const float4*>(&Wproj[d*64 + tx*4]);
        float2 w01 = make_float2(w.x, w.y);
        float2 w23 = make_float2(w.z, w.w);
        float a[8] = {a0.x, a0.y, a0.z, a0.w, a1.x, a1.y, a1.z, a1.w};
        #pragma unroll
        for (int i = 0; i < 8; i++) {
            float2 ad = dup2(a[i]);
            r2[i][0] = ffma2(ad, w01, r2[i][0]);
            r2[i][1] = ffma2(ad, w23, r2[i][1]);
        }
    }
    float4 bb = *reinterpret_cast<const float4*>(&bproj[tx*4]);
    #pragma unroll
    for (int i = 0; i < 8; i++) {
        float4 ov = make_float4(r2[i][0].x + bb.x, r2[i][0].y + bb.y,
                                r2[i][1].x + bb.z, r2[i][1].y + bb.w);
        *reinterpret_cast<float4*>(
            &out[base + (size_t)(q0 + ty*8 + i) * H_ + tx*4]) = ov;
    }
}

// second tuple output: v1 passthrough
__global__ void copy_v1_kernel(const float* __restrict__ v1, float* __restrict__ dst)
{
    int i = blockIdx.x * blockDim.x + threadIdx.x;
    reinterpret_cast<float4*>(dst)[i] = reinterpret_cast<const float4*>(v1)[i];
}

extern "C" void kernel_launch(void* const* d_in, const int* in_sizes, int n_in,
                              void* d_out, int out_size)
{
    const float* x     = (const float*)d_in[0];
    const float* v1    = (const float*)d_in[1];
    const float* Wk    = (const float*)d_in[2];
    const float* Wq    = (const float*)d_in[3];
    const float* Wv    = (const float*)d_in[4];
    const float* Wproj = (const float*)d_in[5];
    const float* bproj = (const float*)d_in[6];
    const float* lamb  = (const float*)d_in[7];
    float* out = (float*)d_out;

    cudaFuncSetAttribute(attn_kernel,
                         cudaFuncAttributeMaxDynamicSharedMemorySize,
                         ATT_SMEM_BYTES);

    qkv_kernel<<<BT_ / QBM, 256>>>(x, v1, Wk, Wq, Wv, lamb);
    attn_kernel<<<16 * B_, 256, ATT_SMEM_BYTES>>>(Wproj, bproj, out);

    if (out_size >= 2 * BT_ * H_) {
        copy_v1_kernel<<<(BT_ * H_ / 4) / 256, 256>>>(v1, out + (size_t)BT_ * H_);
    }
}

// round 5
// speedup vs baseline: 1.9650x; 1.2079x over previous
#include <cuda_runtime.h>
#include <cuda_bf16.h>
#include <math.h>

#define B_  16
#define T_  2048
#define C_  768
#define H_  64
#define BT_ (B_*T_)

// Scratch (allocation-free rule: device globals)
__device__ float g_K[BT_*H_];
__device__ float g_Q[BT_*H_];
__device__ float g_V[BT_*H_];
// W transposed + bf16-split: rows ng = m*64+n (m: 0=K,1=Q,2=V), cols k
__device__ __nv_bfloat16 g_Wt_hi[192*768];
__device__ __nv_bfloat16 g_Wt_lo[192*768];

// ---------------------------------------------------------------------------
// helpers
// ---------------------------------------------------------------------------
__device__ __forceinline__ unsigned smem_u32(const void* p) {
    unsigned a;
    asm("{ .reg .u64 t; cvta.to.shared.u64 t, %1; cvt.u32.u64 %0, t; }"
        : "=r"(a) : "l"(p));
    return a;
}
__device__ __forceinline__ void ldsm4(unsigned* r, unsigned addr) {
    asm volatile("ldmatrix.sync.aligned.m8n8.x4.shared.b16 {%0,%1,%2,%3}, [%4];"
                 : "=r"(r[0]), "=r"(r[1]), "=r"(r[2]), "=r"(r[3]) : "r"(addr));
}
__device__ __forceinline__ void mma_bf16(float* c, const unsigned* a, const unsigned* b) {
    asm volatile(
        "mma.sync.aligned.m16n8k16.row.col.f32.bf16.bf16.f32 "
        "{%0,%1,%2,%3}, {%4,%5,%6,%7}, {%8,%9}, {%0,%1,%2,%3};"
        : "+f"(c[0]), "+f"(c[1]), "+f"(c[2]), "+f"(c[3])
        : "r"(a[0]), "r"(a[1]), "r"(a[2]), "r"(a[3]), "r"(b[0]), "r"(b[1]));
}

union F2U { float2 f; unsigned long long u; };
__device__ __forceinline__ float2 ffma2(float2 a, float2 b, float2 c) {
    F2U A, Bv, C, D;
    A.f = a; Bv.f = b; C.f = c;
    asm("fma.rn.f32x2 %0, %1, %2, %3;"
        : "=l"(D.u) : "l"(A.u), "l"(Bv.u), "l"(C.u));
    return D.f;
}
__device__ __forceinline__ float2 dup2(float a) { return make_float2(a, a); }

// pack 8 fp32 -> uint4 of bf16 hi + uint4 of bf16 lo (split remainder)
__device__ __forceinline__ void split8(const float4& a, const float4& b,
                                       uint4& hi, uint4& lo) {
    float f[8] = {a.x, a.y, a.z, a.w, b.x, b.y, b.z, b.w};
    __nv_bfloat16 h[8], l[8];
    #pragma unroll
    for (int i = 0; i < 8; i++) {
        h[i] = __float2bfloat16(f[i]);
        l[i] = __float2bfloat16(f[i] - __bfloat162float(h[i]));
    }
    __nv_bfloat162 hp[4], lp[4];
    #pragma unroll
    for (int i = 0; i < 4; i++) {
        hp[i] = __halves2bfloat162(h[2*i], h[2*i+1]);
        lp[i] = __halves2bfloat162(l[2*i], l[2*i+1]);
    }
    hi = *reinterpret_cast<uint4*>(hp);
    lo = *reinterpret_cast<uint4*>(lp);
}

// ============================================================================
// W prep: transpose + bf16 hi/lo split.  grid=192, 256 threads.
// ============================================================================
__global__ void wprep_kernel(const float* __restrict__ Wk,
                             const float* __restrict__ Wq,
                             const float* __restrict__ Wv)
{
    int ng = blockIdx.x;              // 0..191
    int m  = ng >> 6;
    int n  = ng & 63;
    const float* __restrict__ W = (m == 0) ? Wk : (m == 1) ? Wq : Wv;
    for (int k = threadIdx.x; k < C_; k += blockDim.x) {
        float w = W[(size_t)k * H_ + n];
        __nv_bfloat16 h = __float2bfloat16(w);
        float rem = w - __bfloat162float(h);
        g_Wt_hi[(size_t)ng * C_ + k] = h;
        g_Wt_lo[(size_t)ng * C_ + k] = __float2bfloat16(rem);
    }
}

// ============================================================================
// QKV GEMM on mma.sync (bf16 hi/lo 3-pass split, fp32 acc).
// Per CTA: 128 rows x 64 cols, K=768 in 12 stages of BK=64.
// grid (3, BT/128): blockIdx.x = matrix (fast -> x shared in L2).
// 256 threads = 8 warps, warp grid 4m x 2n (32x32 per warp).
// ============================================================================
#define QK_STAGES 12
#define SA_HI(b) ((b)*49152)
#define SA_LO(b) ((b)*49152 + 16384)
#define SB_HI(b) ((b)*49152 + 32768)
#define SB_LO(b) ((b)*49152 + 40960)
#define QM_SMEM  98304

__global__ __launch_bounds__(256, 2)
void qkv_mma_kernel(const float* __restrict__ x, const float* __restrict__ v1,
                    const float* __restrict__ lamb_p)
{
    extern __shared__ char smem[];
    const unsigned sb = smem_u32(smem);
    const int tid  = threadIdx.x;
    const int warp = tid >> 5;
    const int lane = tid & 31;
    const int wm   = warp & 3;         // 4 m-groups (32 rows)
    const int wn   = warp >> 2;        // 2 n-groups (32 cols)
    const int mat  = blockIdx.x;       // 0:K 1:Q 2:V
    const int row0 = blockIdx.y * 128;

    // ---- global prefetch registers ----
    float4 pa[4][2];
    uint4  pbh[2], pbl[2];
    const int arow = tid >> 3;          // reused: A row per iter base
    const int ac8  = tid & 7;

    auto load_global = [&](int k0) {
        #pragma unroll
        for (int it = 0; it < 4; it++) {
            int row = arow + it * 32;   // (tid + it*256) >> 3
            const float* p = &x[(size_t)(row0 + row) * C_ + k0 + ac8 * 8];
            pa[it][0] = *reinterpret_cast<const float4*>(p);
            pa[it][1] = *reinterpret_cast<const float4*>(p + 4);
        }
        #pragma unroll
        for (int it = 0; it < 2; it++) {
            int row = arow + it * 32;   // 0..63
            size_t off = (size_t)(mat * 64 + row) * C_ + k0 + ac8 * 8;
            pbh[it] = *reinterpret_cast<const uint4*>(&g_Wt_hi[off]);
            pbl[it] = *reinterpret_cast<const uint4*>(&g_Wt_lo[off]);
        }
    };
    auto store_smem = [&](int buf) {
        #pragma unroll
        for (int it = 0; it < 4; it++) {
            int row = arow + it * 32;
            unsigned boff = row * 128 + ((ac8 * 16) ^ ((row & 7) << 4));
            uint4 hi, lo;
            split8(pa[it][0], pa[it][1], hi, lo);
            *reinterpret_cast<uint4*>(smem + SA_HI(buf) + boff) = hi;
            *reinterpret_cast<uint4*>(smem + SA_LO(buf) + boff) = lo;
        }
        #pragma unroll
        for (int it = 0; it < 2; it++) {
            int row = arow + it * 32;
            unsigned boff = row * 128 + ((ac8 * 16) ^ ((row & 7) << 4));
            *reinterpret_cast<uint4*>(smem + SB_HI(buf) + boff) = pbh[it];
            *reinterpret_cast<uint4*>(smem + SB_LO(buf) + boff) = pbl[it];
        }
    };

    // ---- ldmatrix address components (per-thread invariants) ----
    const int r   = lane & 7;
    const int sel = lane >> 3;
    const unsigned rx = r << 4;
    // A: rows wm*32 + mt*16 + r + (sel&1)*8 ; k-half = (sel>>1)
    unsigned rowA[2], kselA = (sel >> 1) * 16;
    #pragma unroll
    for (int mt = 0; mt < 2; mt++)
        rowA[mt] = (wm * 32 + mt * 16 + r + (sel & 1) * 8) * 128;
    // B: rows wn*32 + pt*16 + r + (sel&2 ? 8:0) ; k-half = (sel&1)
    unsigned rowB[2], kselB = (sel & 1) * 16;
    #pragma unroll
    for (int pt = 0; pt < 2; pt++)
        rowB[pt] = (wn * 32 + pt * 16 + r + ((sel & 2) ? 8 : 0)) * 128;

    float acc[2][4][4];
    #pragma unroll
    for (int mt = 0; mt < 2; mt++)
        #pragma unroll
        for (int nt = 0; nt < 4; nt++)
            #pragma unroll
            for (int e = 0; e < 4; e++) acc[mt][nt][e] = 0.0f;

    load_global(0);
    store_smem(0);
    __syncthreads();

    for (int t = 0; t < QK_STAGES; t++) {
        const int cur = t & 1;
        if (t + 1 < QK_STAGES) load_global((t + 1) * 64);

        const unsigned saH = sb + SA_HI(cur), saL = sb + SA_LO(cur);
        const unsigned sbH = sb + SB_HI(cur), sbL = sb + SB_LO(cur);

        #pragma unroll
        for (int ks = 0; ks < 4; ks++) {
            const unsigned kb = ks * 32;   // k0*2 bytes
            unsigned aH[2][4], aL[2][4], bH[2][4], bL[2][4];
            #pragma unroll
            for (int mt = 0; mt < 2; mt++) {
                unsigned off = ((kb + kselA) ^ rx);
                ldsm4(aH[mt], saH + rowA[mt] + off);
                ldsm4(aL[mt], saL + rowA[mt] + off);
            }
            #pragma unroll
            for (int pt = 0; pt < 2; pt++) {
                unsigned off = ((kb + kselB) ^ rx);
                ldsm4(bH[pt], sbH + rowB[pt] + off);
                ldsm4(bL[pt], sbL + rowB[pt] + off);
            }
            #pragma unroll
            for (int mt = 0; mt < 2; mt++)
                #pragma unroll
                for (int nt = 0; nt < 4; nt++) {
                    const unsigned* bh = &bH[nt >> 1][(nt & 1) * 2];
                    const unsigned* bl = &bL[nt >> 1][(nt & 1) * 2];
                    mma_bf16(acc[mt][nt], aH[mt], bh);
                    mma_bf16(acc[mt][nt], aL[mt], bh);
                    mma_bf16(acc[mt][nt], aH[mt], bl);
                }
        }
        __syncthreads();
        if (t + 1 < QK_STAGES) {
            store_smem((t + 1) & 1);
            __syncthreads();
        }
    }

    // ---- epilogue ----
    const float lam = *lamb_p;
    float* __restrict__ dst = (mat == 0) ? g_K : (mat == 1) ? g_Q : g_V;
    const int qr = lane >> 2;
    const int qc = (lane & 3) * 2;
    #pragma unroll
    for (int mt = 0; mt < 2; mt++)
        #pragma unroll
        for (int nt = 0; nt < 4; nt++)
            #pragma unroll
            for (int half = 0; half < 2; half++) {
                int row = row0 + wm * 32 + mt * 16 + qr + half * 8;
                int col = wn * 32 + nt * 8 + qc;
                float2 v = make_float2(acc[mt][nt][half * 2],
                                       acc[mt][nt][half * 2 + 1]);
                size_t off = (size_t)row * H_ + col;
                if (mat == 2) {
                    float2 vv = *reinterpret_cast<const float2*>(&v1[off]);
                    v.x = (1.0f - lam) * v.x + lam * vv.x;
                    v.y = (1.0f - lam) * v.y + lam * vv.y;
                }
                *reinterpret_cast<float2*>(&dst[off]) = v;
            }
}

// ============================================================================
// Flash attention (unchanged from R3, ~222us): 128q x 128k, f32x2 FMAs.
// ============================================================================
#define QTS 136
#define VTS 68
#define PTS 132
#define ATT_SMEM_FLOATS (64*QTS + 64*QTS + 128*VTS + 128*PTS)
#define ATT_SMEM_BYTES  (ATT_SMEM_FLOATS * 4)

#define SVAL(arr, i, j) (((j) & 1) ? arr[i][(j) >> 1].y : arr[i][(j) >> 1].x)

__global__ __launch_bounds__(256, 1)
void attn_kernel(const float* __restrict__ Wproj,
                 const float* __restrict__ bproj,
                 float* __restrict__ out)
{
    extern __shared__ float sm[];
    float* Qt  = sm;
    float* Kt  = Qt + 64*QTS;
    float* Vs  = Kt + 64*QTS;
    float* Pst = Vs + 128*VTS;

    const int bid = blockIdx.x;
    const int b   = bid & 15;
    const int qt  = 15 - (bid >> 4);
    const int tid = threadIdx.x;
    const int tx  = tid & 15;
    const int ty  = tid >> 4;
    const size_t base = (size_t)b * T_ * H_;
    const int q0 = qt * 128;

    #pragma unroll
    for (int it = 0; it < 8; it++) {
        int idx = tid + it * 256;
        int q = idx & 127, d4 = idx >> 7;
        float4 g = *reinterpret_cast<const float4*>(
            &g_Q[base + (size_t)(q0 + q) * H_ + d4*4]);
        Qt[(d4*4+0)*QTS + q] = g.x;
        Qt[(d4*4+1)*QTS + q] = g.y;
        Qt[(d4*4+2)*QTS + q] = g.z;
        Qt[(d4*4+3)*QTS + q] = g.w;
    }

    float2 o2[8][2];
    float mi[8], li[8];
    #pragma unroll
    for (int i = 0; i < 8; i++) {
        mi[i] = -1e30f; li[i] = 0.0f;
        o2[i][0] = make_float2(0.f, 0.f);
        o2[i][1] = make_float2(0.f, 0.f);
    }

    for (int kb = 0; kb <= qt; kb++) {
        __syncthreads();
        #pragma unroll
        for (int it = 0; it < 8; it++) {
            int idx = tid + it * 256;
            int key = idx & 127, d4 = idx >> 7;
            float4 g = *reinterpret_cast<const float4*>(
                &g_K[base + (size_t)(kb*128 + key) * H_ + d4*4]);
            Kt[(d4*4+0)*QTS + key] = g.x;
            Kt[(d4*4+1)*QTS + key] = g.y;
            Kt[(d4*4+2)*QTS + key] = g.z;
            Kt[(d4*4+3)*QTS + key] = g.w;
        }
        #pragma unroll
        for (int it = 0; it < 8; it++) {
            int idx = tid + it * 256;
            int key = idx >> 4, d4 = idx & 15;
            float4 g = *reinterpret_cast<const float4*>(
                &g_V[base + (size_t)(kb*128 + key) * H_ + d4*4]);
            *reinterpret_cast<float4*>(&Vs[key*VTS + d4*4]) = g;
        }
        __syncthreads();

        float2 s2[8][4];
        #pragma unroll
        for (int i = 0; i < 8; i++)
            #pragma unroll
            for (int jp = 0; jp < 4; jp++) s2[i][jp] = make_float2(0.f, 0.f);

        #pragma unroll 2
        for (int k = 0; k < 64; k++) {
            float4 a0 = *reinterpret_cast<const float4*>(&Qt[k*QTS + ty*8]);
            float4 a1 = *reinterpret_cast<const float4*>(&Qt[k*QTS + ty*8 + 4]);
            float4 b0 = *reinterpret_cast<const float4*>(&Kt[k*QTS + tx*8]);
            float4 b1 = *reinterpret_cast<const float4*>(&Kt[k*QTS + tx*8 + 4]);
            float a[8] = {a0.x, a0.y, a0.z, a0.w, a1.x, a1.y, a1.z, a1.w};
            float2 bb[4] = {make_float2(b0.x, b0.y), make_float2(b0.z, b0.w),
                            make_float2(b1.x, b1.y), make_float2(b1.z, b1.w)};
            #pragma unroll
            for (int i = 0; i < 8; i++) {
                float2 ad = dup2(a[i]);
                #pragma unroll
                for (int jp = 0; jp < 4; jp++)
                    s2[i][jp] = ffma2(ad, bb[jp], s2[i][jp]);
            }
        }

        const float scale = 0.125f;
        if (kb == qt) {
            #pragma unroll
            for (int i = 0; i < 8; i++) {
                int qrow = ty*8 + i;
                #pragma unroll
                for (int jj = 0; jj < 8; jj++) {
                    int key = tx*8 + jj;
                    float v = SVAL(s2, i, jj) * scale;
                    v = (key <= qrow) ? v : -1e30f;
                    if (jj & 1) s2[i][jj>>1].y = v; else s2[i][jj>>1].x = v;
                }
            }
        } else {
            #pragma unroll
            for (int i = 0; i < 8; i++)
                #pragma unroll
                for (int jp = 0; jp < 4; jp++) {
                    s2[i][jp].x *= scale; s2[i][jp].y *= scale;
                }
        }

        #pragma unroll
        for (int i = 0; i < 8; i++) {
            float mx = -1e30f;
            #pragma unroll
            for (int jp = 0; jp < 4; jp++)
                mx = fmaxf(mx, fmaxf(s2[i][jp].x, s2[i][jp].y));
            #pragma unroll
            for (int d = 1; d < 16; d <<= 1)
                mx = fmaxf(mx, __shfl_xor_sync(0xffffffffu, mx, d));
            float mnew = fmaxf(mi[i], mx);
            float corr = __expf(mi[i] - mnew);
            mi[i] = mnew;
            float rs = 0.0f;
            #pragma unroll
            for (int jp = 0; jp < 4; jp++) {
                float px = __expf(s2[i][jp].x - mnew);
                float py = __expf(s2[i][jp].y - mnew);
                s2[i][jp].x = px; s2[i][jp].y = py;
                rs += px + py;
            }
            #pragma unroll
            for (int d = 1; d < 16; d <<= 1)
                rs += __shfl_xor_sync(0xffffffffu, rs, d);
            li[i] = li[i] * corr + rs;
            o2[i][0].x *= corr; o2[i][0].y *= corr;
            o2[i][1].x *= corr; o2[i][1].y *= corr;
        }

        #pragma unroll
        for (int jj = 0; jj < 8; jj++) {
            float4 lo = make_float4(SVAL(s2,0,jj), SVAL(s2,1,jj),
                                    SVAL(s2,2,jj), SVAL(s2,3,jj));
            float4 hi = make_float4(SVAL(s2,4,jj), SVAL(s2,5,jj),
                                    SVAL(s2,6,jj), SVAL(s2,7,jj));
            int pr = jj*16 + tx;
            *reinterpret_cast<float4*>(&Pst[pr*PTS + ty*8])     = lo;
            *reinterpret_cast<float4*>(&Pst[pr*PTS + ty*8 + 4]) = hi;
        }
        __syncthreads();

        #pragma unroll 4
        for (int c = 0; c < 128; c++) {
            int pr = ((c & 7) << 4) | (c >> 3);
            float4 p0 = *reinterpret_cast<const float4*>(&Pst[pr*PTS + ty*8]);
            float4 p1 = *reinterpret_cast<const float4*>(&Pst[pr*PTS + ty*8 + 4]);
            float4 vv = *reinterpret_cast<const float4*>(&Vs[c*VTS + tx*4]);
            float2 v01 = make_float2(vv.x, vv.y);
            float2 v23 = make_float2(vv.z, vv.w);
            float p[8] = {p0.x, p0.y, p0.z, p0.w, p1.x, p1.y, p1.z, p1.w};
            #pragma unroll
            for (int i = 0; i < 8; i++) {
                float2 pd = dup2(p[i]);
                o2[i][0] = ffma2(pd, v01, o2[i][0]);
                o2[i][1] = ffma2(pd, v23, o2[i][1]);
            }
        }
    }

    #pragma unroll
    for (int i = 0; i < 8; i++) {
        float inv = 1.0f / li[i];
        o2[i][0].x *= inv; o2[i][0].y *= inv;
        o2[i][1].x *= inv; o2[i][1].y *= inv;
    }

    __syncthreads();
    #pragma unroll
    for (int j = 0; j < 4; j++) {
        float4 lo = make_float4(SVAL(o2,0,j), SVAL(o2,1,j),
                                SVAL(o2,2,j), SVAL(o2,3,j));
        float4 hi = make_float4(SVAL(o2,4,j), SVAL(o2,5,j),
                                SVAL(o2,6,j), SVAL(o2,7,j));
        int pr = j*16 + tx;
        *reinterpret_cast<float4*>(&Pst[pr*PTS + ty*8])     = lo;
        *reinterpret_cast<float4*>(&Pst[pr*PTS + ty*8 + 4]) = hi;
    }
    __syncthreads();

    float2 r2[8][2];
    #pragma unroll
    for (int i = 0; i < 8; i++) {
        r2[i][0] = make_float2(0.f, 0.f);
        r2[i][1] = make_float2(0.f, 0.f);
    }
    #pragma unroll 4
    for (int d = 0; d < 64; d++) {
        int pr = ((d & 3) << 4) | (d >> 2);
        float4 a0 = *reinterpret_cast<const float4*>(&Pst[pr*PTS + ty*8]);
        float4 a1 = *reinterpret_cast<const float4*>(&Pst[pr*PTS + ty*8 + 4]);
        float4 w  = *reinterpret_cast<const float4*>(&Wproj[d*64 + tx*4]);
        float2 w01 = make_float2(w.x, w.y);
        float2 w23 = make_float2(w.z, w.w);
        float a[8] = {a0.x, a0.y, a0.z, a0.w, a1.x, a1.y, a1.z, a1.w};
        #pragma unroll
        for (int i = 0; i < 8; i++) {
            float2 ad = dup2(a[i]);
            r2[i][0] = ffma2(ad, w01, r2[i][0]);
            r2[i][1] = ffma2(ad, w23, r2[i][1]);
        }
    }
    float4 bb = *reinterpret_cast<const float4*>(&bproj[tx*4]);
    #pragma unroll
    for (int i = 0; i < 8; i++) {
        float4 ov = make_float4(r2[i][0].x + bb.x, r2[i][0].y + bb.y,
                                r2[i][1].x + bb.z, r2[i][1].y + bb.w);
        *reinterpret_cast<float4*>(
            &out[base + (size_t)(q0 + ty*8 + i) * H_ + tx*4]) = ov;
    }
}

// second tuple output: v1 passthrough
__global__ void copy_v1_kernel(const float* __restrict__ v1, float* __restrict__ dst)
{
    int i = blockIdx.x * blockDim.x + threadIdx.x;
    reinterpret_cast<float4*>(dst)[i] = reinterpret_cast<const float4*>(v1)[i];
}

extern "C" void kernel_launch(void* const* d_in, const int* in_sizes, int n_in,
                              void* d_out, int out_size)
{
    const float* x     = (const float*)d_in[0];
    const float* v1    = (const float*)d_in[1];
    const float* Wk    = (const float*)d_in[2];
    const float* Wq    = (const float*)d_in[3];
    const float* Wv    = (const float*)d_in[4];
    const float* Wproj = (const float*)d_in[5];
    const float* bproj = (const float*)d_in[6];
    const float* lamb  = (const float*)d_in[7];
    float* out = (float*)d_out;

    cudaFuncSetAttribute(qkv_mma_kernel,
                         cudaFuncAttributeMaxDynamicSharedMemorySize,
                         QM_SMEM);
    cudaFuncSetAttribute(attn_kernel,
                         cudaFuncAttributeMaxDynamicSharedMemorySize,
                         ATT_SMEM_BYTES);

    wprep_kernel<<<192, 256>>>(Wk, Wq, Wv);
    qkv_mma_kernel<<<dim3(3, BT_ / 128), 256, QM_SMEM>>>(x, v1, lamb);
    attn_kernel<<<16 * B_, 256, ATT_SMEM_BYTES>>>(Wproj, bproj, out);

    if (out_size >= 2 * BT_ * H_) {
        copy_v1_kernel<<<(BT_ * H_ / 4) / 256, 256>>>(v1, out + (size_t)BT_ * H_);
    }
}

// round 6
// speedup vs baseline: 3.5614x; 1.8124x over previous
#include <cuda_runtime.h>
#include <cuda_bf16.h>
#include <math.h>

#define B_  16
#define T_  2048
#define C_  768
#define H_  64
#define BT_ (B_*T_)

// Scratch (allocation-free rule: device globals) — bf16 hi/lo split Q/K/V
__device__ __nv_bfloat16 g_Qh[BT_*H_], g_Ql[BT_*H_];
__device__ __nv_bfloat16 g_Kh[BT_*H_], g_Kl[BT_*H_];
__device__ __nv_bfloat16 g_Vh[BT_*H_], g_Vl[BT_*H_];
// W transposed + bf16-split: rows ng = m*64+n (m: 0=K,1=Q,2=V), cols k
__device__ __nv_bfloat16 g_Wt_hi[192*768];
__device__ __nv_bfloat16 g_Wt_lo[192*768];

// ---------------------------------------------------------------------------
// helpers
// ---------------------------------------------------------------------------
__device__ __forceinline__ unsigned smem_u32(const void* p) {
    unsigned a;
    asm("{ .reg .u64 t; cvta.to.shared.u64 t, %1; cvt.u32.u64 %0, t; }"
        : "=r"(a) : "l"(p));
    return a;
}
__device__ __forceinline__ void ldsm4(unsigned* r, unsigned addr) {
    asm volatile("ldmatrix.sync.aligned.m8n8.x4.shared.b16 {%0,%1,%2,%3}, [%4];"
                 : "=r"(r[0]), "=r"(r[1]), "=r"(r[2]), "=r"(r[3]) : "r"(addr));
}
__device__ __forceinline__ void ldsm4_t(unsigned* r, unsigned addr) {
    asm volatile("ldmatrix.sync.aligned.m8n8.x4.trans.shared.b16 {%0,%1,%2,%3}, [%4];"
                 : "=r"(r[0]), "=r"(r[1]), "=r"(r[2]), "=r"(r[3]) : "r"(addr));
}
__device__ __forceinline__ void mma_bf16(float* c, const unsigned* a, const unsigned* b) {
    asm volatile(
        "mma.sync.aligned.m16n8k16.row.col.f32.bf16.bf16.f32 "
        "{%0,%1,%2,%3}, {%4,%5,%6,%7}, {%8,%9}, {%0,%1,%2,%3};"
        : "+f"(c[0]), "+f"(c[1]), "+f"(c[2]), "+f"(c[3])
        : "r"(a[0]), "r"(a[1]), "r"(a[2]), "r"(a[3]), "r"(b[0]), "r"(b[1]));
}
__device__ __forceinline__ void cp_async16(unsigned dst, const void* src) {
    asm volatile("cp.async.cg.shared.global [%0], [%1], 16;"
                 :: "r"(dst), "l"(src) : "memory");
}
__device__ __forceinline__ void cp_commit() {
    asm volatile("cp.async.commit_group;" ::: "memory");
}
template<int N> __device__ __forceinline__ void cp_wait() {
    asm volatile("cp.async.wait_group %0;" :: "n"(N) : "memory");
}

union F2U { float2 f; unsigned long long u; };
__device__ __forceinline__ float2 ffma2(float2 a, float2 b, float2 c) {
    F2U A, Bv, C, D;
    A.f = a; Bv.f = b; C.f = c;
    asm("fma.rn.f32x2 %0, %1, %2, %3;"
        : "=l"(D.u) : "l"(A.u), "l"(Bv.u), "l"(C.u));
    return D.f;
}
__device__ __forceinline__ float2 dup2(float a) { return make_float2(a, a); }

// pack two fp32 into bf16x2 hi + bf16x2 lo (split remainder)
__device__ __forceinline__ void split2(float x, float y, unsigned& hi, unsigned& lo) {
    __nv_bfloat16 hx = __float2bfloat16(x);
    __nv_bfloat16 hy = __float2bfloat16(y);
    __nv_bfloat16 lx = __float2bfloat16(x - __bfloat162float(hx));
    __nv_bfloat16 ly = __float2bfloat16(y - __bfloat162float(hy));
    __nv_bfloat162 h2 = __halves2bfloat162(hx, hy);
    __nv_bfloat162 l2 = __halves2bfloat162(lx, ly);
    hi = *reinterpret_cast<unsigned*>(&h2);
    lo = *reinterpret_cast<unsigned*>(&l2);
}

// pack 8 fp32 -> uint4 hi + uint4 lo
__device__ __forceinline__ void split8(const float4& a, const float4& b,
                                       uint4& hi, uint4& lo) {
    split2(a.x, a.y, hi.x, lo.x);
    split2(a.z, a.w, hi.y, lo.y);
    split2(b.x, b.y, hi.z, lo.z);
    split2(b.z, b.w, hi.w, lo.w);
}

// ============================================================================
// W prep: transpose + bf16 hi/lo split.  grid=192, 256 threads.
// ============================================================================
__global__ void wprep_kernel(const float* __restrict__ Wk,
                             const float* __restrict__ Wq,
                             const float* __restrict__ Wv)
{
    int ng = blockIdx.x;
    int m  = ng >> 6;
    int n  = ng & 63;
    const float* __restrict__ W = (m == 0) ? Wk : (m == 1) ? Wq : Wv;
    for (int k = threadIdx.x; k < C_; k += blockDim.x) {
        float w = W[(size_t)k * H_ + n];
        __nv_bfloat16 h = __float2bfloat16(w);
        g_Wt_hi[(size_t)ng * C_ + k] = h;
        g_Wt_lo[(size_t)ng * C_ + k] = __float2bfloat16(w - __bfloat162float(h));
    }
}

// ============================================================================
// QKV GEMM on mma.sync (bf16 hi/lo 3-pass split, fp32 acc).
// Epilogue emits hi/lo bf16 splits of K/Q/V (V includes lambda mix).
// ============================================================================
#define QK_STAGES 12
#define SA_HI(b) ((b)*49152)
#define SA_LO(b) ((b)*49152 + 16384)
#define SB_HI(b) ((b)*49152 + 32768)
#define SB_LO(b) ((b)*49152 + 40960)
#define QM_SMEM  98304

__global__ __launch_bounds__(256, 2)
void qkv_mma_kernel(const float* __restrict__ x, const float* __restrict__ v1,
                    const float* __restrict__ lamb_p)
{
    extern __shared__ char smem[];
    const unsigned sb = smem_u32(smem);
    const int tid  = threadIdx.x;
    const int warp = tid >> 5;
    const int lane = tid & 31;
    const int wm   = warp & 3;
    const int wn   = warp >> 2;
    const int mat  = blockIdx.x;       // 0:K 1:Q 2:V
    const int row0 = blockIdx.y * 128;

    float4 pa[4][2];
    uint4  pbh[2], pbl[2];
    const int arow = tid >> 3;
    const int ac8  = tid & 7;

    auto load_global = [&](int k0) {
        #pragma unroll
        for (int it = 0; it < 4; it++) {
            int row = arow + it * 32;
            const float* p = &x[(size_t)(row0 + row) * C_ + k0 + ac8 * 8];
            pa[it][0] = *reinterpret_cast<const float4*>(p);
            pa[it][1] = *reinterpret_cast<const float4*>(p + 4);
        }
        #pragma unroll
        for (int it = 0; it < 2; it++) {
            int row = arow + it * 32;
            size_t off = (size_t)(mat * 64 + row) * C_ + k0 + ac8 * 8;
            pbh[it] = *reinterpret_cast<const uint4*>(&g_Wt_hi[off]);
            pbl[it] = *reinterpret_cast<const uint4*>(&g_Wt_lo[off]);
        }
    };
    auto store_smem = [&](int buf) {
        #pragma unroll
        for (int it = 0; it < 4; it++) {
            int row = arow + it * 32;
            unsigned boff = row * 128 + ((ac8 * 16) ^ ((row & 7) << 4));
            uint4 hi, lo;
            split8(pa[it][0], pa[it][1], hi, lo);
            *reinterpret_cast<uint4*>(smem + SA_HI(buf) + boff) = hi;
            *reinterpret_cast<uint4*>(smem + SA_LO(buf) + boff) = lo;
        }
        #pragma unroll
        for (int it = 0; it < 2; it++) {
            int row = arow + it * 32;
            unsigned boff = row * 128 + ((ac8 * 16) ^ ((row & 7) << 4));
            *reinterpret_cast<uint4*>(smem + SB_HI(buf) + boff) = pbh[it];
            *reinterpret_cast<uint4*>(smem + SB_LO(buf) + boff) = pbl[it];
        }
    };

    const int r   = lane & 7;
    const int sel = lane >> 3;
    const unsigned rx = r << 4;
    unsigned rowA[2], kselA = (sel >> 1) * 16;
    #pragma unroll
    for (int mt = 0; mt < 2; mt++)
        rowA[mt] = (wm * 32 + mt * 16 + r + (sel & 1) * 8) * 128;
    unsigned rowB[2], kselB = (sel & 1) * 16;
    #pragma unroll
    for (int pt = 0; pt < 2; pt++)
        rowB[pt] = (wn * 32 + pt * 16 + r + ((sel & 2) ? 8 : 0)) * 128;

    float acc[2][4][4];
    #pragma unroll
    for (int mt = 0; mt < 2; mt++)
        #pragma unroll
        for (int nt = 0; nt < 4; nt++)
            #pragma unroll
            for (int e = 0; e < 4; e++) acc[mt][nt][e] = 0.0f;

    load_global(0);
    store_smem(0);
    __syncthreads();

    for (int t = 0; t < QK_STAGES; t++) {
        const int cur = t & 1;
        if (t + 1 < QK_STAGES) load_global((t + 1) * 64);

        const unsigned saH = sb + SA_HI(cur), saL = sb + SA_LO(cur);
        const unsigned sbH = sb + SB_HI(cur), sbL = sb + SB_LO(cur);

        #pragma unroll
        for (int ks = 0; ks < 4; ks++) {
            const unsigned kb = ks * 32;
            unsigned aH[2][4], aL[2][4], bH[2][4], bL[2][4];
            #pragma unroll
            for (int mt = 0; mt < 2; mt++) {
                unsigned off = ((kb + kselA) ^ rx);
                ldsm4(aH[mt], saH + rowA[mt] + off);
                ldsm4(aL[mt], saL + rowA[mt] + off);
            }
            #pragma unroll
            for (int pt = 0; pt < 2; pt++) {
                unsigned off = ((kb + kselB) ^ rx);
                ldsm4(bH[pt], sbH + rowB[pt] + off);
                ldsm4(bL[pt], sbL + rowB[pt] + off);
            }
            #pragma unroll
            for (int mt = 0; mt < 2; mt++)
                #pragma unroll
                for (int nt = 0; nt < 4; nt++) {
                    const unsigned* bh = &bH[nt >> 1][(nt & 1) * 2];
                    const unsigned* bl = &bL[nt >> 1][(nt & 1) * 2];
                    mma_bf16(acc[mt][nt], aH[mt], bh);
                    mma_bf16(acc[mt][nt], aL[mt], bh);
                    mma_bf16(acc[mt][nt], aH[mt], bl);
                }
        }
        __syncthreads();
        if (t + 1 < QK_STAGES) {
            store_smem((t + 1) & 1);
            __syncthreads();
        }
    }

    // ---- epilogue: split to bf16 hi/lo globals ----
    const float lam = *lamb_p;
    __nv_bfloat16* dh = (mat == 0) ? g_Kh : (mat == 1) ? g_Qh : g_Vh;
    __nv_bfloat16* dl = (mat == 0) ? g_Kl : (mat == 1) ? g_Ql : g_Vl;
    const int qr = lane >> 2;
    const int qc = (lane & 3) * 2;
    #pragma unroll
    for (int mt = 0; mt < 2; mt++)
        #pragma unroll
        for (int nt = 0; nt < 4; nt++)
            #pragma unroll
            for (int half = 0; half < 2; half++) {
                int row = row0 + wm * 32 + mt * 16 + qr + half * 8;
                int col = wn * 32 + nt * 8 + qc;
                float vx = acc[mt][nt][half * 2];
                float vy = acc[mt][nt][half * 2 + 1];
                size_t off = (size_t)row * H_ + col;
                if (mat == 2) {
                    float2 vv = *reinterpret_cast<const float2*>(&v1[off]);
                    vx = (1.0f - lam) * vx + lam * vv.x;
                    vy = (1.0f - lam) * vy + lam * vv.y;
                }
                unsigned hi, lo;
                split2(vx, vy, hi, lo);
                *reinterpret_cast<unsigned*>(&dh[off]) = hi;
                *reinterpret_cast<unsigned*>(&dl[off]) = lo;
            }
}

// ============================================================================
// Tensor-core flash attention.
// Per CTA: 128 q rows, 8 warps (each m16), k-blocks of 64 keys.
// S = QK^T and O += PV on mma.m16n8k16.bf16, hi/lo 3-pass splits.
// K/V tiles via cp.async double-buffering (pure bf16 copies).
// smem: [0,34816) Qh/Ql then reused as Ot(fp32); KV bufs at 34816 + b*32768.
// ============================================================================
#define AT_QO   34816
#define AT_KV(b) (AT_QO + (b)*32768)
#define AT_SMEM (AT_QO + 2*32768)
#define OTS 132

__global__ __launch_bounds__(256, 1)
void attn_tc_kernel(const float* __restrict__ Wproj,
                    const float* __restrict__ bproj,
                    float* __restrict__ out)
{
    extern __shared__ char smem[];
    const unsigned sb = smem_u32(smem);
    const int bid  = blockIdx.x;
    const int b    = bid & 15;
    const int qt   = 15 - (bid >> 4);        // heavy tiles first
    const int tid  = threadIdx.x;
    const int warp = tid >> 5;
    const int lane = tid & 31;
    const int r    = lane & 7;
    const int sel  = lane >> 3;
    const unsigned rx = r << 4;
    const int q0   = qt * 128;
    const int rowbase = b * T_;              // row index base into [BT] arrays
    const int nkb  = 2 * qt + 2;

    // ---- cp.async K/V tile issue: 64 keys x 64 d, 4 arrays (Kh,Kl,Vh,Vl) ----
    auto issue_kv = [&](int kb, int buf) {
        const __nv_bfloat16* srcs[4] = {g_Kh, g_Kl, g_Vh, g_Vl};
        const unsigned dbase = sb + AT_KV(buf);
        #pragma unroll
        for (int it = 0; it < 8; it++) {
            int idx = tid + it * 256;          // 0..2047
            int arr = idx >> 9;
            int row = (idx >> 3) & 63;
            int c   = idx & 7;
            const void* src = &srcs[arr][(size_t)(rowbase + kb * 64 + row) * H_ + c * 8];
            unsigned dst = dbase + arr * 8192 + row * 128 + ((c * 16) ^ ((row & 7) << 4));
            cp_async16(dst, src);
        }
        cp_commit();
    };

    issue_kv(0, 0);

    // ---- stage Q tile (hi/lo) into smem once ----
    #pragma unroll
    for (int it = 0; it < 8; it++) {
        int idx = tid + it * 256;              // 0..2047
        int arr = idx >> 10;
        int row = (idx >> 3) & 127;
        int c   = idx & 7;
        const __nv_bfloat16* src = (arr ? g_Ql : g_Qh);
        uint4 v = *reinterpret_cast<const uint4*>(
            &src[(size_t)(rowbase + q0 + row) * H_ + c * 8]);
        *reinterpret_cast<uint4*>(
            smem + arr * 16384 + row * 128 + ((c * 16) ^ ((row & 7) << 4))) = v;
    }
    cp_wait<0>();
    __syncthreads();

    // ---- Q fragments (held in registers for whole kernel) ----
    unsigned qh[4][4], ql[4][4];
    {
        int rowA = warp * 16 + r + (sel & 1) * 8;
        unsigned rb = rowA * 128;
        #pragma unroll
        for (int ks = 0; ks < 4; ks++) {
            unsigned off = ((ks * 32 + (sel >> 1) * 16) ^ rx);
            ldsm4(qh[ks], sb + rb + off);
            ldsm4(ql[ks], sb + 16384 + rb + off);
        }
    }

    float oacc[8][4];
    #pragma unroll
    for (int j = 0; j < 8; j++)
        #pragma unroll
        for (int e = 0; e < 4; e++) oacc[j][e] = 0.0f;
    float mi[2] = {-1e30f, -1e30f}, li[2] = {0.0f, 0.0f};

    for (int kb = 0; kb < nkb; kb++) {
        const unsigned kvb = sb + AT_KV(kb & 1);
        cp_wait<0>();
        __syncthreads();
        if (kb + 1 < nkb) issue_kv(kb + 1, (kb + 1) & 1);

        // ---- S = Q K^T ----
        float sacc[8][4];
        #pragma unroll
        for (int j = 0; j < 8; j++)
            #pragma unroll
            for (int e = 0; e < 4; e++) sacc[j][e] = 0.0f;

        #pragma unroll
        for (int ks = 0; ks < 4; ks++) {
            unsigned kh[4][4], kl[4][4];
            const int rk = r + ((sel & 2) ? 8 : 0);
            const unsigned koff = ((ks * 32 + (sel & 1) * 16) ^ rx);
            #pragma unroll
            for (int u = 0; u < 4; u++) {
                unsigned rb = (u * 16 + rk) * 128;
                ldsm4(kh[u], kvb + rb + koff);
                ldsm4(kl[u], kvb + 8192 + rb + koff);
            }
            #pragma unroll
            for (int u = 0; u < 4; u++)
                #pragma unroll
                for (int nn = 0; nn < 2; nn++) {
                    const unsigned* bh = &kh[u][nn * 2];
                    const unsigned* bl = &kl[u][nn * 2];
                    float* c = sacc[u * 2 + nn];
                    mma_bf16(c, qh[ks], bh);
                    mma_bf16(c, ql[ks], bh);
                    mma_bf16(c, qh[ks], bl);
                }
        }

        // ---- scale + causal mask ----
        const float scale = 0.125f;
        if (kb * 64 + 63 > q0 + warp * 16) {
            #pragma unroll
            for (int j = 0; j < 8; j++)
                #pragma unroll
                for (int e = 0; e < 4; e++) {
                    int key  = kb * 64 + j * 8 + (lane & 3) * 2 + (e & 1);
                    int qrow = q0 + warp * 16 + (lane >> 2) + (e >> 1) * 8;
                    float v = sacc[j][e] * scale;
                    sacc[j][e] = (key <= qrow) ? v : -1e30f;
                }
        } else {
            #pragma unroll
            for (int j = 0; j < 8; j++)
                #pragma unroll
                for (int e = 0; e < 4; e++) sacc[j][e] *= scale;
        }

        // ---- online softmax (rows live in quads: shfl xor 1,2) ----
        #pragma unroll
        for (int h = 0; h < 2; h++) {
            float mx = -1e30f;
            #pragma unroll
            for (int j = 0; j < 8; j++)
                mx = fmaxf(mx, fmaxf(sacc[j][h*2], sacc[j][h*2+1]));
            mx = fmaxf(mx, __shfl_xor_sync(0xffffffffu, mx, 1));
            mx = fmaxf(mx, __shfl_xor_sync(0xffffffffu, mx, 2));
            float mnew = fmaxf(mi[h], mx);
            float corr = __expf(mi[h] - mnew);
            mi[h] = mnew;
            float rs = 0.0f;
            #pragma unroll
            for (int j = 0; j < 8; j++) {
                float p0 = __expf(sacc[j][h*2]   - mnew);
                float p1 = __expf(sacc[j][h*2+1] - mnew);
                sacc[j][h*2] = p0; sacc[j][h*2+1] = p1;
                rs += p0 + p1;
            }
            rs += __shfl_xor_sync(0xffffffffu, rs, 1);
            rs += __shfl_xor_sync(0xffffffffu, rs, 2);
            li[h] = li[h] * corr + rs;
            #pragma unroll
            for (int j = 0; j < 8; j++) {
                oacc[j][h*2]   *= corr;
                oacc[j][h*2+1] *= corr;
            }
        }

        // ---- P -> bf16 hi/lo A-fragments (FA2 repack) ----
        unsigned pfh[4][4], pfl[4][4];
        #pragma unroll
        for (int kt = 0; kt < 4; kt++) {
            split2(sacc[2*kt][0],   sacc[2*kt][1],   pfh[kt][0], pfl[kt][0]);
            split2(sacc[2*kt][2],   sacc[2*kt][3],   pfh[kt][1], pfl[kt][1]);
            split2(sacc[2*kt+1][0], sacc[2*kt+1][1], pfh[kt][2], pfl[kt][2]);
            split2(sacc[2*kt+1][2], sacc[2*kt+1][3], pfh[kt][3], pfl[kt][3]);
        }

        // ---- O += P V ----
        #pragma unroll
        for (int kt = 0; kt < 4; kt++) {
            unsigned vh[4][4], vl[4][4];
            const unsigned rb = (kt * 16 + (sel & 1) * 8 + r) * 128;
            #pragma unroll
            for (int u = 0; u < 4; u++) {
                unsigned off = (((2 * u + (sel >> 1)) * 16) ^ rx);
                ldsm4_t(vh[u], kvb + 16384 + rb + off);
                ldsm4_t(vl[u], kvb + 24576 + rb + off);
            }
            #pragma unroll
            for (int u = 0; u < 4; u++)
                #pragma unroll
                for (int nn = 0; nn < 2; nn++) {
                    const unsigned* bh = &vh[u][nn * 2];
                    const unsigned* bl = &vl[u][nn * 2];
                    float* c = oacc[u * 2 + nn];
                    mma_bf16(c, pfh[kt], bh);
                    mma_bf16(c, pfl[kt], bh);
                    mma_bf16(c, pfh[kt], bl);
                }
        }
    }

    // ---- epilogue: normalize, stage O^T (reuse Q smem), fused Wproj ----
    __syncthreads();
    float* Ot = reinterpret_cast<float*>(smem);
    {
        float inv0 = 1.0f / li[0], inv1 = 1.0f / li[1];
        #pragma unroll
        for (int j = 0; j < 8; j++)
            #pragma unroll
            for (int e = 0; e < 4; e++) {
                int qrel = warp * 16 + (lane >> 2) + (e >> 1) * 8;
                int d    = j * 8 + (lane & 3) * 2 + (e & 1);
                Ot[d * OTS + qrel] = oacc[j][e] * ((e >> 1) ? inv1 : inv0);
            }
    }
    __syncthreads();

    const int tx = tid & 15;
    const int ty = tid >> 4;
    float2 r2[8][2];
    #pragma unroll
    for (int i = 0; i < 8; i++) {
        r2[i][0] = make_float2(0.f, 0.f);
        r2[i][1] = make_float2(0.f, 0.f);
    }
    #pragma unroll 4
    for (int d = 0; d < 64; d++) {
        float4 a0 = *reinterpret_cast<const float4*>(&Ot[d * OTS + ty * 8]);
        float4 a1 = *reinterpret_cast<const float4*>(&Ot[d * OTS + ty * 8 + 4]);
        float4 w  = *reinterpret_cast<const float4*>(&Wproj[d * 64 + tx * 4]);
        float2 w01 = make_float2(w.x, w.y);
        float2 w23 = make_float2(w.z, w.w);
        float a[8] = {a0.x, a0.y, a0.z, a0.w, a1.x, a1.y, a1.z, a1.w};
        #pragma unroll
        for (int i = 0; i < 8; i++) {
            float2 ad = dup2(a[i]);
            r2[i][0] = ffma2(ad, w01, r2[i][0]);
            r2[i][1] = ffma2(ad, w23, r2[i][1]);
        }
    }
    float4 bb = *reinterpret_cast<const float4*>(&bproj[tx * 4]);
    const size_t baseo = (size_t)b * T_ * H_;
    #pragma unroll
    for (int i = 0; i < 8; i++) {
        float4 ov = make_float4(r2[i][0].x + bb.x, r2[i][0].y + bb.y,
                                r2[i][1].x + bb.z, r2[i][1].y + bb.w);
        *reinterpret_cast<float4*>(
            &out[baseo + (size_t)(q0 + ty * 8 + i) * H_ + tx * 4]) = ov;
    }
}

// second tuple output: v1 passthrough
__global__ void copy_v1_kernel(const float* __restrict__ v1, float* __restrict__ dst)
{
    int i = blockIdx.x * blockDim.x + threadIdx.x;
    reinterpret_cast<float4*>(dst)[i] = reinterpret_cast<const float4*>(v1)[i];
}

extern "C" void kernel_launch(void* const* d_in, const int* in_sizes, int n_in,
                              void* d_out, int out_size)
{
    const float* x     = (const float*)d_in[0];
    const float* v1    = (const float*)d_in[1];
    const float* Wk    = (const float*)d_in[2];
    const float* Wq    = (const float*)d_in[3];
    const float* Wv    = (const float*)d_in[4];
    const float* Wproj = (const float*)d_in[5];
    const float* bproj = (const float*)d_in[6];
    const float* lamb  = (const float*)d_in[7];
    float* out = (float*)d_out;

    cudaFuncSetAttribute(qkv_mma_kernel,
                         cudaFuncAttributeMaxDynamicSharedMemorySize, QM_SMEM);
    cudaFuncSetAttribute(attn_tc_kernel,
                         cudaFuncAttributeMaxDynamicSharedMemorySize, AT_SMEM);

    wprep_kernel<<<192, 256>>>(Wk, Wq, Wv);
    qkv_mma_kernel<<<dim3(3, BT_ / 128), 256, QM_SMEM>>>(x, v1, lamb);
    attn_tc_kernel<<<16 * B_, 256, AT_SMEM>>>(Wproj, bproj, out);

    if (out_size >= 2 * BT_ * H_) {
        copy_v1_kernel<<<(BT_ * H_ / 4) / 256, 256>>>(v1, out + (size_t)BT_ * H_);
    }
}

// round 7
// speedup vs baseline: 4.6353x; 1.3015x over previous
#include <cuda_runtime.h>
#include <cuda_fp16.h>
#include <math.h>

#define B_  16
#define T_  2048
#define C_  768
#define H_  64
#define BT_ (B_*T_)

// Scratch (allocation-free rule: device globals)
// Q needs hi/lo (A operand in S); K, V need only hi (B operands).
__device__ __half g_Qh[BT_*H_], g_Ql[BT_*H_];
__device__ __half g_Kh[BT_*H_];
__device__ __half g_Vh[BT_*H_];
// W transposed, fp16-rounded: rows ng = m*64+n (m: 0=K,1=Q,2=V), cols k
__device__ __half g_Wt_h[192*768];

// ---------------------------------------------------------------------------
// helpers
// ---------------------------------------------------------------------------
__device__ __forceinline__ unsigned smem_u32(const void* p) {
    unsigned a;
    asm("{ .reg .u64 t; cvta.to.shared.u64 t, %1; cvt.u32.u64 %0, t; }"
        : "=r"(a) : "l"(p));
    return a;
}
__device__ __forceinline__ void ldsm4(unsigned* r, unsigned addr) {
    asm volatile("ldmatrix.sync.aligned.m8n8.x4.shared.b16 {%0,%1,%2,%3}, [%4];"
                 : "=r"(r[0]), "=r"(r[1]), "=r"(r[2]), "=r"(r[3]) : "r"(addr));
}
__device__ __forceinline__ void ldsm4_t(unsigned* r, unsigned addr) {
    asm volatile("ldmatrix.sync.aligned.m8n8.x4.trans.shared.b16 {%0,%1,%2,%3}, [%4];"
                 : "=r"(r[0]), "=r"(r[1]), "=r"(r[2]), "=r"(r[3]) : "r"(addr));
}
__device__ __forceinline__ void mma_f16(float* c, const unsigned* a, const unsigned* b) {
    asm volatile(
        "mma.sync.aligned.m16n8k16.row.col.f32.f16.f16.f32 "
        "{%0,%1,%2,%3}, {%4,%5,%6,%7}, {%8,%9}, {%0,%1,%2,%3};"
        : "+f"(c[0]), "+f"(c[1]), "+f"(c[2]), "+f"(c[3])
        : "r"(a[0]), "r"(a[1]), "r"(a[2]), "r"(a[3]), "r"(b[0]), "r"(b[1]));
}
__device__ __forceinline__ void cp_async16(unsigned dst, const void* src) {
    asm volatile("cp.async.cg.shared.global [%0], [%1], 16;"
                 :: "r"(dst), "l"(src) : "memory");
}
__device__ __forceinline__ void cp_commit() {
    asm volatile("cp.async.commit_group;" ::: "memory");
}
template<int N> __device__ __forceinline__ void cp_wait() {
    asm volatile("cp.async.wait_group %0;" :: "n"(N) : "memory");
}

union F2U { float2 f; unsigned long long u; };
__device__ __forceinline__ float2 ffma2(float2 a, float2 b, float2 c) {
    F2U A, Bv, C, D;
    A.f = a; Bv.f = b; C.f = c;
    asm("fma.rn.f32x2 %0, %1, %2, %3;"
        : "=l"(D.u) : "l"(A.u), "l"(Bv.u), "l"(C.u));
    return D.f;
}
__device__ __forceinline__ float2 dup2(float a) { return make_float2(a, a); }

// pack two fp32 into f16x2 hi + f16x2 lo (split remainder)
__device__ __forceinline__ void split2(float x, float y, unsigned& hi, unsigned& lo) {
    __half hx = __float2half_rn(x);
    __half hy = __float2half_rn(y);
    __half lx = __float2half_rn(x - __half2float(hx));
    __half ly = __float2half_rn(y - __half2float(hy));
    __half2 h2 = __halves2half2(hx, hy);
    __half2 l2 = __halves2half2(lx, ly);
    hi = *reinterpret_cast<unsigned*>(&h2);
    lo = *reinterpret_cast<unsigned*>(&l2);
}
// pack two fp32 into f16x2 (plain round)
__device__ __forceinline__ unsigned round2(float x, float y) {
    __half2 h2 = __halves2half2(__float2half_rn(x), __float2half_rn(y));
    return *reinterpret_cast<unsigned*>(&h2);
}
// pack 8 fp32 -> uint4 hi + uint4 lo
__device__ __forceinline__ void split8(const float4& a, const float4& b,
                                       uint4& hi, uint4& lo) {
    split2(a.x, a.y, hi.x, lo.x);
    split2(a.z, a.w, hi.y, lo.y);
    split2(b.x, b.y, hi.z, lo.z);
    split2(b.z, b.w, hi.w, lo.w);
}

// ============================================================================
// W prep: transpose + fp16 round.  grid=192, 256 threads.
// ============================================================================
__global__ void wprep_kernel(const float* __restrict__ Wk,
                             const float* __restrict__ Wq,
                             const float* __restrict__ Wv)
{
    int ng = blockIdx.x;
    int m  = ng >> 6;
    int n  = ng & 63;
    const float* __restrict__ W = (m == 0) ? Wk : (m == 1) ? Wq : Wv;
    for (int k = threadIdx.x; k < C_; k += blockDim.x) {
        g_Wt_h[(size_t)ng * C_ + k] = __float2half_rn(W[(size_t)k * H_ + n]);
    }
}

// ============================================================================
// QKV GEMM on mma.sync fp16: D = (xh+xl) . Wh  (2-pass split, fp32 acc).
// Per CTA: 128 rows x 64 cols, K=768 in 12 stages of BK=64.
// grid (3, BT/128): blockIdx.x = matrix (fast -> x shared in L2).
// ============================================================================
#define QK_STAGES 12
#define SA_HI(b) ((b)*40960)
#define SA_LO(b) ((b)*40960 + 16384)
#define SB_HI(b) ((b)*40960 + 32768)
#define QM_SMEM  81920

__global__ __launch_bounds__(256, 2)
void qkv_mma_kernel(const float* __restrict__ x, const float* __restrict__ v1,
                    const float* __restrict__ lamb_p)
{
    extern __shared__ char smem[];
    const unsigned sb = smem_u32(smem);
    const int tid  = threadIdx.x;
    const int warp = tid >> 5;
    const int lane = tid & 31;
    const int wm   = warp & 3;
    const int wn   = warp >> 2;
    const int mat  = blockIdx.x;       // 0:K 1:Q 2:V
    const int row0 = blockIdx.y * 128;

    float4 pa[4][2];
    uint4  pbh[2];
    const int arow = tid >> 3;
    const int ac8  = tid & 7;

    auto load_global = [&](int k0) {
        #pragma unroll
        for (int it = 0; it < 4; it++) {
            int row = arow + it * 32;
            const float* p = &x[(size_t)(row0 + row) * C_ + k0 + ac8 * 8];
            pa[it][0] = *reinterpret_cast<const float4*>(p);
            pa[it][1] = *reinterpret_cast<const float4*>(p + 4);
        }
        #pragma unroll
        for (int it = 0; it < 2; it++) {
            int row = arow + it * 32;
            size_t off = (size_t)(mat * 64 + row) * C_ + k0 + ac8 * 8;
            pbh[it] = *reinterpret_cast<const uint4*>(&g_Wt_h[off]);
        }
    };
    auto store_smem = [&](int buf) {
        #pragma unroll
        for (int it = 0; it < 4; it++) {
            int row = arow + it * 32;
            unsigned boff = row * 128 + ((ac8 * 16) ^ ((row & 7) << 4));
            uint4 hi, lo;
            split8(pa[it][0], pa[it][1], hi, lo);
            *reinterpret_cast<uint4*>(smem + SA_HI(buf) + boff) = hi;
            *reinterpret_cast<uint4*>(smem + SA_LO(buf) + boff) = lo;
        }
        #pragma unroll
        for (int it = 0; it < 2; it++) {
            int row = arow + it * 32;
            unsigned boff = row * 128 + ((ac8 * 16) ^ ((row & 7) << 4));
            *reinterpret_cast<uint4*>(smem + SB_HI(buf) + boff) = pbh[it];
        }
    };

    const int r   = lane & 7;
    const int sel = lane >> 3;
    const unsigned rx = r << 4;
    unsigned rowA[2], kselA = (sel >> 1) * 16;
    #pragma unroll
    for (int mt = 0; mt < 2; mt++)
        rowA[mt] = (wm * 32 + mt * 16 + r + (sel & 1) * 8) * 128;
    unsigned rowB[2], kselB = (sel & 1) * 16;
    #pragma unroll
    for (int pt = 0; pt < 2; pt++)
        rowB[pt] = (wn * 32 + pt * 16 + r + ((sel & 2) ? 8 : 0)) * 128;

    float acc[2][4][4];
    #pragma unroll
    for (int mt = 0; mt < 2; mt++)
        #pragma unroll
        for (int nt = 0; nt < 4; nt++)
            #pragma unroll
            for (int e = 0; e < 4; e++) acc[mt][nt][e] = 0.0f;

    load_global(0);
    store_smem(0);
    __syncthreads();

    for (int t = 0; t < QK_STAGES; t++) {
        const int cur = t & 1;
        if (t + 1 < QK_STAGES) load_global((t + 1) * 64);

        const unsigned saH = sb + SA_HI(cur), saL = sb + SA_LO(cur);
        const unsigned sbH = sb + SB_HI(cur);

        #pragma unroll
        for (int ks = 0; ks < 4; ks++) {
            const unsigned kb = ks * 32;
            unsigned aH[2][4], aL[2][4], bH[2][4];
            #pragma unroll
            for (int mt = 0; mt < 2; mt++) {
                unsigned off = ((kb + kselA) ^ rx);
                ldsm4(aH[mt], saH + rowA[mt] + off);
                ldsm4(aL[mt], saL + rowA[mt] + off);
            }
            #pragma unroll
            for (int pt = 0; pt < 2; pt++) {
                unsigned off = ((kb + kselB) ^ rx);
                ldsm4(bH[pt], sbH + rowB[pt] + off);
            }
            #pragma unroll
            for (int mt = 0; mt < 2; mt++)
                #pragma unroll
                for (int nt = 0; nt < 4; nt++) {
                    const unsigned* bh = &bH[nt >> 1][(nt & 1) * 2];
                    mma_f16(acc[mt][nt], aH[mt], bh);
                    mma_f16(acc[mt][nt], aL[mt], bh);
                }
        }
        __syncthreads();
        if (t + 1 < QK_STAGES) {
            store_smem((t + 1) & 1);
            __syncthreads();
        }
    }

    // ---- epilogue ----
    const float lam = *lamb_p;
    const int qr = lane >> 2;
    const int qc = (lane & 3) * 2;
    #pragma unroll
    for (int mt = 0; mt < 2; mt++)
        #pragma unroll
        for (int nt = 0; nt < 4; nt++)
            #pragma unroll
            for (int half = 0; half < 2; half++) {
                int row = row0 + wm * 32 + mt * 16 + qr + half * 8;
                int col = wn * 32 + nt * 8 + qc;
                float vx = acc[mt][nt][half * 2];
                float vy = acc[mt][nt][half * 2 + 1];
                size_t off = (size_t)row * H_ + col;
                if (mat == 0) {
                    *reinterpret_cast<unsigned*>(&g_Kh[off]) = round2(vx, vy);
                } else if (mat == 1) {
                    unsigned hi, lo;
                    split2(vx, vy, hi, lo);
                    *reinterpret_cast<unsigned*>(&g_Qh[off]) = hi;
                    *reinterpret_cast<unsigned*>(&g_Ql[off]) = lo;
                } else {
                    float2 vv = *reinterpret_cast<const float2*>(&v1[off]);
                    vx = (1.0f - lam) * vx + lam * vv.x;
                    vy = (1.0f - lam) * vy + lam * vv.y;
                    *reinterpret_cast<unsigned*>(&g_Vh[off]) = round2(vx, vy);
                }
            }
}

// ============================================================================
// Tensor-core flash attention (fp16 2-pass).
// Per CTA: 128 q rows, 8 warps (each m16), k-blocks of 64 keys.
// S = (Qh+Ql).Kh^T ; O += (Ph+Pl).Vh. cp.async double-buffered K/V (hi only).
// smem: [0,34816) Qh/Ql then reused as Ot(fp32); KV bufs 16KB each.
// ============================================================================
#define AT_QO   34816
#define AT_KV(b) (AT_QO + (b)*16384)
#define AT_SMEM (AT_QO + 2*16384)
#define OTS 132

__global__ __launch_bounds__(256, 1)
void attn_tc_kernel(const float* __restrict__ Wproj,
                    const float* __restrict__ bproj,
                    float* __restrict__ out)
{
    extern __shared__ char smem[];
    const unsigned sb = smem_u32(smem);
    const int bid  = blockIdx.x;
    const int b    = bid & 15;
    const int qt   = 15 - (bid >> 4);        // heavy tiles first
    const int tid  = threadIdx.x;
    const int warp = tid >> 5;
    const int lane = tid & 31;
    const int r    = lane & 7;
    const int sel  = lane >> 3;
    const unsigned rx = r << 4;
    const int q0   = qt * 128;
    const int rowbase = b * T_;
    const int nkb  = 2 * qt + 2;

    // ---- cp.async K/V tile: 64 keys x 64 d, 2 arrays (Kh, Vh) ----
    auto issue_kv = [&](int kb, int buf) {
        const __half* srcs[2] = {g_Kh, g_Vh};
        const unsigned dbase = sb + AT_KV(buf);
        #pragma unroll
        for (int it = 0; it < 4; it++) {
            int idx = tid + it * 256;          // 0..1023
            int arr = idx >> 9;
            int row = (idx >> 3) & 63;
            int c   = idx & 7;
            const void* src = &srcs[arr][(size_t)(rowbase + kb * 64 + row) * H_ + c * 8];
            unsigned dst = dbase + arr * 8192 + row * 128 + ((c * 16) ^ ((row & 7) << 4));
            cp_async16(dst, src);
        }
        cp_commit();
    };

    issue_kv(0, 0);

    // ---- stage Q tile (hi/lo) into smem once ----
    #pragma unroll
    for (int it = 0; it < 8; it++) {
        int idx = tid + it * 256;              // 0..2047
        int arr = idx >> 10;
        int row = (idx >> 3) & 127;
        int c   = idx & 7;
        const __half* src = (arr ? g_Ql : g_Qh);
        uint4 v = *reinterpret_cast<const uint4*>(
            &src[(size_t)(rowbase + q0 + row) * H_ + c * 8]);
        *reinterpret_cast<uint4*>(
            smem + arr * 16384 + row * 128 + ((c * 16) ^ ((row & 7) << 4))) = v;
    }
    cp_wait<0>();
    __syncthreads();

    // ---- Q fragments (registers for whole kernel) ----
    unsigned qh[4][4], ql[4][4];
    {
        int rowA = warp * 16 + r + (sel & 1) * 8;
        unsigned rb = rowA * 128;
        #pragma unroll
        for (int ks = 0; ks < 4; ks++) {
            unsigned off = ((ks * 32 + (sel >> 1) * 16) ^ rx);
            ldsm4(qh[ks], sb + rb + off);
            ldsm4(ql[ks], sb + 16384 + rb + off);
        }
    }

    float oacc[8][4];
    #pragma unroll
    for (int j = 0; j < 8; j++)
        #pragma unroll
        for (int e = 0; e < 4; e++) oacc[j][e] = 0.0f;
    float mi[2] = {-1e30f, -1e30f}, li[2] = {0.0f, 0.0f};

    for (int kb = 0; kb < nkb; kb++) {
        const unsigned kvb = sb + AT_KV(kb & 1);
        cp_wait<0>();
        __syncthreads();
        if (kb + 1 < nkb) issue_kv(kb + 1, (kb + 1) & 1);

        // ---- S = Q K^T ----
        float sacc[8][4];
        #pragma unroll
        for (int j = 0; j < 8; j++)
            #pragma unroll
            for (int e = 0; e < 4; e++) sacc[j][e] = 0.0f;

        #pragma unroll
        for (int ks = 0; ks < 4; ks++) {
            unsigned kh[4][4];
            const int rk = r + ((sel & 2) ? 8 : 0);
            const unsigned koff = ((ks * 32 + (sel & 1) * 16) ^ rx);
            #pragma unroll
            for (int u = 0; u < 4; u++) {
                unsigned rb = (u * 16 + rk) * 128;
                ldsm4(kh[u], kvb + rb + koff);
            }
            #pragma unroll
            for (int u = 0; u < 4; u++)
                #pragma unroll
                for (int nn = 0; nn < 2; nn++) {
                    const unsigned* bh = &kh[u][nn * 2];
                    float* c = sacc[u * 2 + nn];
                    mma_f16(c, qh[ks], bh);
                    mma_f16(c, ql[ks], bh);
                }
        }

        // ---- scale + causal mask ----
        const float scale = 0.125f;
        if (kb * 64 + 63 > q0 + warp * 16) {
            #pragma unroll
            for (int j = 0; j < 8; j++)
                #pragma unroll
                for (int e = 0; e < 4; e++) {
                    int key  = kb * 64 + j * 8 + (lane & 3) * 2 + (e & 1);
                    int qrow = q0 + warp * 16 + (lane >> 2) + (e >> 1) * 8;
                    float v = sacc[j][e] * scale;
                    sacc[j][e] = (key <= qrow) ? v : -1e30f;
                }
        } else {
            #pragma unroll
            for (int j = 0; j < 8; j++)
                #pragma unroll
                for (int e = 0; e < 4; e++) sacc[j][e] *= scale;
        }

        // ---- online softmax (rows in quads: shfl xor 1,2) ----
        #pragma unroll
        for (int h = 0; h < 2; h++) {
            float mx = -1e30f;
            #pragma unroll
            for (int j = 0; j < 8; j++)
                mx = fmaxf(mx, fmaxf(sacc[j][h*2], sacc[j][h*2+1]));
            mx = fmaxf(mx, __shfl_xor_sync(0xffffffffu, mx, 1));
            mx = fmaxf(mx, __shfl_xor_sync(0xffffffffu, mx, 2));
            float mnew = fmaxf(mi[h], mx);
            float corr = __expf(mi[h] - mnew);
            mi[h] = mnew;
            float rs = 0.0f;
            #pragma unroll
            for (int j = 0; j < 8; j++) {
                float p0 = __expf(sacc[j][h*2]   - mnew);
                float p1 = __expf(sacc[j][h*2+1] - mnew);
                sacc[j][h*2] = p0; sacc[j][h*2+1] = p1;
                rs += p0 + p1;
            }
            rs += __shfl_xor_sync(0xffffffffu, rs, 1);
            rs += __shfl_xor_sync(0xffffffffu, rs, 2);
            li[h] = li[h] * corr + rs;
            #pragma unroll
            for (int j = 0; j < 8; j++) {
                oacc[j][h*2]   *= corr;
                oacc[j][h*2+1] *= corr;
            }
        }

        // ---- P -> fp16 hi/lo A-fragments (FA2 repack) ----
        unsigned pfh[4][4], pfl[4][4];
        #pragma unroll
        for (int kt = 0; kt < 4; kt++) {
            split2(sacc[2*kt][0],   sacc[2*kt][1],   pfh[kt][0], pfl[kt][0]);
            split2(sacc[2*kt][2],   sacc[2*kt][3],   pfh[kt][1], pfl[kt][1]);
            split2(sacc[2*kt+1][0], sacc[2*kt+1][1], pfh[kt][2], pfl[kt][2]);
            split2(sacc[2*kt+1][2], sacc[2*kt+1][3], pfh[kt][3], pfl[kt][3]);
        }

        // ---- O += P V ----
        #pragma unroll
        for (int kt = 0; kt < 4; kt++) {
            unsigned vh[4][4];
            const unsigned rb = (kt * 16 + (sel & 1) * 8 + r) * 128;
            #pragma unroll
            for (int u = 0; u < 4; u++) {
                unsigned off = (((2 * u + (sel >> 1)) * 16) ^ rx);
                ldsm4_t(vh[u], kvb + 8192 + rb + off);
            }
            #pragma unroll
            for (int u = 0; u < 4; u++)
                #pragma unroll
                for (int nn = 0; nn < 2; nn++) {
                    const unsigned* bh = &vh[u][nn * 2];
                    float* c = oacc[u * 2 + nn];
                    mma_f16(c, pfh[kt], bh);
                    mma_f16(c, pfl[kt], bh);
                }
        }
    }

    // ---- epilogue: normalize, stage O^T (reuse Q smem), fused Wproj ----
    __syncthreads();
    float* Ot = reinterpret_cast<float*>(smem);
    {
        float inv0 = 1.0f / li[0], inv1 = 1.0f / li[1];
        #pragma unroll
        for (int j = 0; j < 8; j++)
            #pragma unroll
            for (int e = 0; e < 4; e++) {
                int qrel = warp * 16 + (lane >> 2) + (e >> 1) * 8;
                int d    = j * 8 + (lane & 3) * 2 + (e & 1);
                Ot[d * OTS + qrel] = oacc[j][e] * ((e >> 1) ? inv1 : inv0);
            }
    }
    __syncthreads();

    const int tx = tid & 15;
    const int ty = tid >> 4;
    float2 r2[8][2];
    #pragma unroll
    for (int i = 0; i < 8; i++) {
        r2[i][0] = make_float2(0.f, 0.f);
        r2[i][1] = make_float2(0.f, 0.f);
    }
    #pragma unroll 4
    for (int d = 0; d < 64; d++) {
        float4 a0 = *reinterpret_cast<const float4*>(&Ot[d * OTS + ty * 8]);
        float4 a1 = *reinterpret_cast<const float4*>(&Ot[d * OTS + ty * 8 + 4]);
        float4 w  = *reinterpret_cast<const float4*>(&Wproj[d * 64 + tx * 4]);
        float2 w01 = make_float2(w.x, w.y);
        float2 w23 = make_float2(w.z, w.w);
        float a[8] = {a0.x, a0.y, a0.z, a0.w, a1.x, a1.y, a1.z, a1.w};
        #pragma unroll
        for (int i = 0; i < 8; i++) {
            float2 ad = dup2(a[i]);
            r2[i][0] = ffma2(ad, w01, r2[i][0]);
            r2[i][1] = ffma2(ad, w23, r2[i][1]);
        }
    }
    float4 bb = *reinterpret_cast<const float4*>(&bproj[tx * 4]);
    const size_t baseo = (size_t)b * T_ * H_;
    #pragma unroll
    for (int i = 0; i < 8; i++) {
        float4 ov = make_float4(r2[i][0].x + bb.x, r2[i][0].y + bb.y,
                                r2[i][1].x + bb.z, r2[i][1].y + bb.w);
        *reinterpret_cast<float4*>(
            &out[baseo + (size_t)(q0 + ty * 8 + i) * H_ + tx * 4]) = ov;
    }
}

// second tuple output: v1 passthrough
__global__ void copy_v1_kernel(const float* __restrict__ v1, float* __restrict__ dst)
{
    int i = blockIdx.x * blockDim.x + threadIdx.x;
    reinterpret_cast<float4*>(dst)[i] = reinterpret_cast<const float4*>(v1)[i];
}

extern "C" void kernel_launch(void* const* d_in, const int* in_sizes, int n_in,
                              void* d_out, int out_size)
{
    const float* x     = (const float*)d_in[0];
    const float* v1    = (const float*)d_in[1];
    const float* Wk    = (const float*)d_in[2];
    const float* Wq    = (const float*)d_in[3];
    const float* Wv    = (const float*)d_in[4];
    const float* Wproj = (const float*)d_in[5];
    const float* bproj = (const float*)d_in[6];
    const float* lamb  = (const float*)d_in[7];
    float* out = (float*)d_out;

    cudaFuncSetAttribute(qkv_mma_kernel,
                         cudaFuncAttributeMaxDynamicSharedMemorySize, QM_SMEM);
    cudaFuncSetAttribute(attn_tc_kernel,
                         cudaFuncAttributeMaxDynamicSharedMemorySize, AT_SMEM);

    wprep_kernel<<<192, 256>>>(Wk, Wq, Wv);
    qkv_mma_kernel<<<dim3(3, BT_ / 128), 256, QM_SMEM>>>(x, v1, lamb);
    attn_tc_kernel<<<16 * B_, 256, AT_SMEM>>>(Wproj, bproj, out);

    if (out_size >= 2 * BT_ * H_) {
        copy_v1_kernel<<<(BT_ * H_ / 4) / 256, 256>>>(v1, out + (size_t)BT_ * H_);
    }
}

// round 8
// speedup vs baseline: 5.2606x; 1.1349x over previous
#include <cuda_runtime.h>
#include <cuda_fp16.h>
#include <math.h>

#define B_  16
#define T_  2048
#define C_  768
#define H_  64
#define BT_ (B_*T_)

// Scratch (allocation-free rule: device globals)
// Q, K, V all stored fp16-rounded (Q hi/lo no longer needed: S is 1-pass).
// x is kept 2-pass inside qkv (A split there) since its error feeds everything.
__device__ __half g_Qh[BT_*H_];
__device__ __half g_Kh[BT_*H_];
__device__ __half g_Vh[BT_*H_];
// W transposed, fp16-rounded: rows ng = m*64+n (m: 0=K,1=Q,2=V), cols k
__device__ __half g_Wt_h[192*768];

// ---------------------------------------------------------------------------
// helpers
// ---------------------------------------------------------------------------
__device__ __forceinline__ unsigned smem_u32(const void* p) {
    unsigned a;
    asm("{ .reg .u64 t; cvta.to.shared.u64 t, %1; cvt.u32.u64 %0, t; }"
        : "=r"(a) : "l"(p));
    return a;
}
__device__ __forceinline__ void ldsm4(unsigned* r, unsigned addr) {
    asm volatile("ldmatrix.sync.aligned.m8n8.x4.shared.b16 {%0,%1,%2,%3}, [%4];"
                 : "=r"(r[0]), "=r"(r[1]), "=r"(r[2]), "=r"(r[3]) : "r"(addr));
}
__device__ __forceinline__ void ldsm4_t(unsigned* r, unsigned addr) {
    asm volatile("ldmatrix.sync.aligned.m8n8.x4.trans.shared.b16 {%0,%1,%2,%3}, [%4];"
                 : "=r"(r[0]), "=r"(r[1]), "=r"(r[2]), "=r"(r[3]) : "r"(addr));
}
__device__ __forceinline__ void mma_f16(float* c, const unsigned* a, const unsigned* b) {
    asm volatile(
        "mma.sync.aligned.m16n8k16.row.col.f32.f16.f16.f32 "
        "{%0,%1,%2,%3}, {%4,%5,%6,%7}, {%8,%9}, {%0,%1,%2,%3};"
        : "+f"(c[0]), "+f"(c[1]), "+f"(c[2]), "+f"(c[3])
        : "r"(a[0]), "r"(a[1]), "r"(a[2]), "r"(a[3]), "r"(b[0]), "r"(b[1]));
}
__device__ __forceinline__ void cp_async16(unsigned dst, const void* src) {
    asm volatile("cp.async.cg.shared.global [%0], [%1], 16;"
                 :: "r"(dst), "l"(src) : "memory");
}
__device__ __forceinline__ void cp_commit() {
    asm volatile("cp.async.commit_group;" ::: "memory");
}
template<int N> __device__ __forceinline__ void cp_wait() {
    asm volatile("cp.async.wait_group %0;" :: "n"(N) : "memory");
}

union F2U { float2 f; unsigned long long u; };
__device__ __forceinline__ float2 ffma2(float2 a, float2 b, float2 c) {
    F2U A, Bv, C, D;
    A.f = a; Bv.f = b; C.f = c;
    asm("fma.rn.f32x2 %0, %1, %2, %3;"
        : "=l"(D.u) : "l"(A.u), "l"(Bv.u), "l"(C.u));
    return D.f;
}
__device__ __forceinline__ float2 dup2(float a) { return make_float2(a, a); }

// pack two fp32 into f16x2 hi + f16x2 lo (split remainder)
__device__ __forceinline__ void split2(float x, float y, unsigned& hi, unsigned& lo) {
    __half hx = __float2half_rn(x);
    __half hy = __float2half_rn(y);
    __half lx = __float2half_rn(x - __half2float(hx));
    __half ly = __float2half_rn(y - __half2float(hy));
    __half2 h2 = __halves2half2(hx, hy);
    __half2 l2 = __halves2half2(lx, ly);
    hi = *reinterpret_cast<unsigned*>(&h2);
    lo = *reinterpret_cast<unsigned*>(&l2);
}
// pack two fp32 into f16x2 (plain round)
__device__ __forceinline__ unsigned round2(float x, float y) {
    __half2 h2 = __halves2half2(__float2half_rn(x), __float2half_rn(y));
    return *reinterpret_cast<unsigned*>(&h2);
}
// pack 8 fp32 -> uint4 hi + uint4 lo
__device__ __forceinline__ void split8(const float4& a, const float4& b,
                                       uint4& hi, uint4& lo) {
    split2(a.x, a.y, hi.x, lo.x);
    split2(a.z, a.w, hi.y, lo.y);
    split2(b.x, b.y, hi.z, lo.z);
    split2(b.z, b.w, hi.w, lo.w);
}

// ============================================================================
// Prep: W transpose + fp16 round (blocks 0..191), v1 passthrough copy
// (blocks 192..2239). One launch covers both.
// ============================================================================
__global__ void prep_kernel(const float* __restrict__ Wk,
                            const float* __restrict__ Wq,
                            const float* __restrict__ Wv,
                            const float* __restrict__ v1,
                            float* __restrict__ v1dst)
{
    if (blockIdx.x < 192) {
        int ng = blockIdx.x;
        int m  = ng >> 6;
        int n  = ng & 63;
        const float* __restrict__ W = (m == 0) ? Wk : (m == 1) ? Wq : Wv;
        for (int k = threadIdx.x; k < C_; k += blockDim.x) {
            g_Wt_h[(size_t)ng * C_ + k] = __float2half_rn(W[(size_t)k * H_ + n]);
        }
    } else if (v1dst != nullptr) {
        int i = (blockIdx.x - 192) * blockDim.x + threadIdx.x;
        reinterpret_cast<float4*>(v1dst)[i] =
            reinterpret_cast<const float4*>(v1)[i];
    }
}

// ============================================================================
// QKV GEMM on mma.sync fp16: D = (xh+xl) . Wh  (2-pass split, fp32 acc).
// Per CTA: 128 rows x 64 cols, K=768 in 12 stages of BK=64.
// grid (3, BT/128): blockIdx.x = matrix (fast -> x shared in L2).
// ============================================================================
#define QK_STAGES 12
#define SA_HI(b) ((b)*40960)
#define SA_LO(b) ((b)*40960 + 16384)
#define SB_HI(b) ((b)*40960 + 32768)
#define QM_SMEM  81920

__global__ __launch_bounds__(256, 2)
void qkv_mma_kernel(const float* __restrict__ x, const float* __restrict__ v1,
                    const float* __restrict__ lamb_p)
{
    extern __shared__ char smem[];
    const unsigned sb = smem_u32(smem);
    const int tid  = threadIdx.x;
    const int warp = tid >> 5;
    const int lane = tid & 31;
    const int wm   = warp & 3;
    const int wn   = warp >> 2;
    const int mat  = blockIdx.x;       // 0:K 1:Q 2:V
    const int row0 = blockIdx.y * 128;

    float4 pa[4][2];
    uint4  pbh[2];
    const int arow = tid >> 3;
    const int ac8  = tid & 7;

    auto load_global = [&](int k0) {
        #pragma unroll
        for (int it = 0; it < 4; it++) {
            int row = arow + it * 32;
            const float* p = &x[(size_t)(row0 + row) * C_ + k0 + ac8 * 8];
            pa[it][0] = *reinterpret_cast<const float4*>(p);
            pa[it][1] = *reinterpret_cast<const float4*>(p + 4);
        }
        #pragma unroll
        for (int it = 0; it < 2; it++) {
            int row = arow + it * 32;
            size_t off = (size_t)(mat * 64 + row) * C_ + k0 + ac8 * 8;
            pbh[it] = *reinterpret_cast<const uint4*>(&g_Wt_h[off]);
        }
    };
    auto store_smem = [&](int buf) {
        #pragma unroll
        for (int it = 0; it < 4; it++) {
            int row = arow + it * 32;
            unsigned boff = row * 128 + ((ac8 * 16) ^ ((row & 7) << 4));
            uint4 hi, lo;
            split8(pa[it][0], pa[it][1], hi, lo);
            *reinterpret_cast<uint4*>(smem + SA_HI(buf) + boff) = hi;
            *reinterpret_cast<uint4*>(smem + SA_LO(buf) + boff) = lo;
        }
        #pragma unroll
        for (int it = 0; it < 2; it++) {
            int row = arow + it * 32;
            unsigned boff = row * 128 + ((ac8 * 16) ^ ((row & 7) << 4));
            *reinterpret_cast<uint4*>(smem + SB_HI(buf) + boff) = pbh[it];
        }
    };

    const int r   = lane & 7;
    const int sel = lane >> 3;
    const unsigned rx = r << 4;
    unsigned rowA[2], kselA = (sel >> 1) * 16;
    #pragma unroll
    for (int mt = 0; mt < 2; mt++)
        rowA[mt] = (wm * 32 + mt * 16 + r + (sel & 1) * 8) * 128;
    unsigned rowB[2], kselB = (sel & 1) * 16;
    #pragma unroll
    for (int pt = 0; pt < 2; pt++)
        rowB[pt] = (wn * 32 + pt * 16 + r + ((sel & 2) ? 8 : 0)) * 128;

    float acc[2][4][4];
    #pragma unroll
    for (int mt = 0; mt < 2; mt++)
        #pragma unroll
        for (int nt = 0; nt < 4; nt++)
            #pragma unroll
            for (int e = 0; e < 4; e++) acc[mt][nt][e] = 0.0f;

    load_global(0);
    store_smem(0);
    __syncthreads();

    for (int t = 0; t < QK_STAGES; t++) {
        const int cur = t & 1;
        if (t + 1 < QK_STAGES) load_global((t + 1) * 64);

        const unsigned saH = sb + SA_HI(cur), saL = sb + SA_LO(cur);
        const unsigned sbH = sb + SB_HI(cur);

        #pragma unroll
        for (int ks = 0; ks < 4; ks++) {
            const unsigned kb = ks * 32;
            unsigned aH[2][4], aL[2][4], bH[2][4];
            #pragma unroll
            for (int mt = 0; mt < 2; mt++) {
                unsigned off = ((kb + kselA) ^ rx);
                ldsm4(aH[mt], saH + rowA[mt] + off);
                ldsm4(aL[mt], saL + rowA[mt] + off);
            }
            #pragma unroll
            for (int pt = 0; pt < 2; pt++) {
                unsigned off = ((kb + kselB) ^ rx);
                ldsm4(bH[pt], sbH + rowB[pt] + off);
            }
            #pragma unroll
            for (int mt = 0; mt < 2; mt++)
                #pragma unroll
                for (int nt = 0; nt < 4; nt++) {
                    const unsigned* bh = &bH[nt >> 1][(nt & 1) * 2];
                    mma_f16(acc[mt][nt], aH[mt], bh);
                    mma_f16(acc[mt][nt], aL[mt], bh);
                }
        }
        __syncthreads();
        if (t + 1 < QK_STAGES) {
            store_smem((t + 1) & 1);
            __syncthreads();
        }
    }

    // ---- epilogue ----
    const float lam = *lamb_p;
    const int qr = lane >> 2;
    const int qc = (lane & 3) * 2;
    #pragma unroll
    for (int mt = 0; mt < 2; mt++)
        #pragma unroll
        for (int nt = 0; nt < 4; nt++)
            #pragma unroll
            for (int half = 0; half < 2; half++) {
                int row = row0 + wm * 32 + mt * 16 + qr + half * 8;
                int col = wn * 32 + nt * 8 + qc;
                float vx = acc[mt][nt][half * 2];
                float vy = acc[mt][nt][half * 2 + 1];
                size_t off = (size_t)row * H_ + col;
                if (mat == 0) {
                    *reinterpret_cast<unsigned*>(&g_Kh[off]) = round2(vx, vy);
                } else if (mat == 1) {
                    *reinterpret_cast<unsigned*>(&g_Qh[off]) = round2(vx, vy);
                } else {
                    float2 vv = *reinterpret_cast<const float2*>(&v1[off]);
                    vx = (1.0f - lam) * vx + lam * vv.x;
                    vy = (1.0f - lam) * vy + lam * vv.y;
                    *reinterpret_cast<unsigned*>(&g_Vh[off]) = round2(vx, vy);
                }
            }
}

// ============================================================================
// Tensor-core flash attention (fp16 1-pass S, 1-pass PV).
// Per CTA: 128 q rows, 8 warps (each m16), k-blocks of 64 keys.
// S = Qh.Kh^T ; O += Ph.Vh. cp.async double-buffered K/V.
// smem: [0,16384) Qh, [0,33792) reused as Ot(fp32); KV bufs 16KB each.
// ============================================================================
#define AT_QO   34816
#define AT_KV(b) (AT_QO + (b)*16384)
#define AT_SMEM (AT_QO + 2*16384)
#define OTS 132

__global__ __launch_bounds__(256, 1)
void attn_tc_kernel(const float* __restrict__ Wproj,
                    const float* __restrict__ bproj,
                    float* __restrict__ out)
{
    extern __shared__ char smem[];
    const unsigned sb = smem_u32(smem);
    const int bid  = blockIdx.x;
    const int b    = bid & 15;
    const int qt   = 15 - (bid >> 4);        // heavy tiles first
    const int tid  = threadIdx.x;
    const int warp = tid >> 5;
    const int lane = tid & 31;
    const int r    = lane & 7;
    const int sel  = lane >> 3;
    const unsigned rx = r << 4;
    const int q0   = qt * 128;
    const int rowbase = b * T_;
    const int nkb  = 2 * qt + 2;

    // ---- cp.async K/V tile: 64 keys x 64 d, 2 arrays (Kh, Vh) ----
    auto issue_kv = [&](int kb, int buf) {
        const __half* srcs[2] = {g_Kh, g_Vh};
        const unsigned dbase = sb + AT_KV(buf);
        #pragma unroll
        for (int it = 0; it < 4; it++) {
            int idx = tid + it * 256;          // 0..1023
            int arr = idx >> 9;
            int row = (idx >> 3) & 63;
            int c   = idx & 7;
            const void* src = &srcs[arr][(size_t)(rowbase + kb * 64 + row) * H_ + c * 8];
            unsigned dst = dbase + arr * 8192 + row * 128 + ((c * 16) ^ ((row & 7) << 4));
            cp_async16(dst, src);
        }
        cp_commit();
    };

    issue_kv(0, 0);

    // ---- stage Q tile (hi only) into smem once ----
    #pragma unroll
    for (int it = 0; it < 4; it++) {
        int idx = tid + it * 256;              // 0..1023
        int row = (idx >> 3) & 127;
        int c   = idx & 7;
        uint4 v = *reinterpret_cast<const uint4*>(
            &g_Qh[(size_t)(rowbase + q0 + row) * H_ + c * 8]);
        *reinterpret_cast<uint4*>(
            smem + row * 128 + ((c * 16) ^ ((row & 7) << 4))) = v;
    }
    cp_wait<0>();
    __syncthreads();

    // ---- Q fragments (registers for whole kernel) ----
    unsigned qh[4][4];
    {
        int rowA = warp * 16 + r + (sel & 1) * 8;
        unsigned rb = rowA * 128;
        #pragma unroll
        for (int ks = 0; ks < 4; ks++) {
            unsigned off = ((ks * 32 + (sel >> 1) * 16) ^ rx);
            ldsm4(qh[ks], sb + rb + off);
        }
    }

    float oacc[8][4];
    #pragma unroll
    for (int j = 0; j < 8; j++)
        #pragma unroll
        for (int e = 0; e < 4; e++) oacc[j][e] = 0.0f;
    float mi[2] = {-1e30f, -1e30f}, li[2] = {0.0f, 0.0f};

    for (int kb = 0; kb < nkb; kb++) {
        const unsigned kvb = sb + AT_KV(kb & 1);
        cp_wait<0>();
        __syncthreads();
        if (kb + 1 < nkb) issue_kv(kb + 1, (kb + 1) & 1);

        // ---- S = Q K^T (1 pass) ----
        float sacc[8][4];
        #pragma unroll
        for (int j = 0; j < 8; j++)
            #pragma unroll
            for (int e = 0; e < 4; e++) sacc[j][e] = 0.0f;

        #pragma unroll
        for (int ks = 0; ks < 4; ks++) {
            unsigned kh[4][4];
            const int rk = r + ((sel & 2) ? 8 : 0);
            const unsigned koff = ((ks * 32 + (sel & 1) * 16) ^ rx);
            #pragma unroll
            for (int u = 0; u < 4; u++) {
                unsigned rb = (u * 16 + rk) * 128;
                ldsm4(kh[u], kvb + rb + koff);
            }
            #pragma unroll
            for (int u = 0; u < 4; u++)
                #pragma unroll
                for (int nn = 0; nn < 2; nn++)
                    mma_f16(sacc[u * 2 + nn], qh[ks], &kh[u][nn * 2]);
        }

        // ---- scale + causal mask ----
        const float scale = 0.125f;
        if (kb * 64 + 63 > q0 + warp * 16) {
            #pragma unroll
            for (int j = 0; j < 8; j++)
                #pragma unroll
                for (int e = 0; e < 4; e++) {
                    int key  = kb * 64 + j * 8 + (lane & 3) * 2 + (e & 1);
                    int qrow = q0 + warp * 16 + (lane >> 2) + (e >> 1) * 8;
                    float v = sacc[j][e] * scale;
                    sacc[j][e] = (key <= qrow) ? v : -1e30f;
                }
        } else {
            #pragma unroll
            for (int j = 0; j < 8; j++)
                #pragma unroll
                for (int e = 0; e < 4; e++) sacc[j][e] *= scale;
        }

        // ---- online softmax (rows in quads: shfl xor 1,2) ----
        #pragma unroll
        for (int h = 0; h < 2; h++) {
            float mx = -1e30f;
            #pragma unroll
            for (int j = 0; j < 8; j++)
                mx = fmaxf(mx, fmaxf(sacc[j][h*2], sacc[j][h*2+1]));
            mx = fmaxf(mx, __shfl_xor_sync(0xffffffffu, mx, 1));
            mx = fmaxf(mx, __shfl_xor_sync(0xffffffffu, mx, 2));
            float mnew = fmaxf(mi[h], mx);
            float corr = __expf(mi[h] - mnew);
            mi[h] = mnew;
            float rs = 0.0f;
            #pragma unroll
            for (int j = 0; j < 8; j++) {
                float p0 = __expf(sacc[j][h*2]   - mnew);
                float p1 = __expf(sacc[j][h*2+1] - mnew);
                sacc[j][h*2] = p0; sacc[j][h*2+1] = p1;
                rs += p0 + p1;
            }
            rs += __shfl_xor_sync(0xffffffffu, rs, 1);
            rs += __shfl_xor_sync(0xffffffffu, rs, 2);
            li[h] = li[h] * corr + rs;
            #pragma unroll
            for (int j = 0; j < 8; j++) {
                oacc[j][h*2]   *= corr;
                oacc[j][h*2+1] *= corr;
            }
        }

        // ---- P -> fp16 A-fragments (round, FA2 repack) ----
        unsigned pfh[4][4];
        #pragma unroll
        for (int kt = 0; kt < 4; kt++) {
            pfh[kt][0] = round2(sacc[2*kt][0],   sacc[2*kt][1]);
            pfh[kt][1] = round2(sacc[2*kt][2],   sacc[2*kt][3]);
            pfh[kt][2] = round2(sacc[2*kt+1][0], sacc[2*kt+1][1]);
            pfh[kt][3] = round2(sacc[2*kt+1][2], sacc[2*kt+1][3]);
        }

        // ---- O += P V (1 pass) ----
        #pragma unroll
        for (int kt = 0; kt < 4; kt++) {
            unsigned vh[4][4];
            const unsigned rb = (kt * 16 + (sel & 1) * 8 + r) * 128;
            #pragma unroll
            for (int u = 0; u < 4; u++) {
                unsigned off = (((2 * u + (sel >> 1)) * 16) ^ rx);
                ldsm4_t(vh[u], kvb + 8192 + rb + off);
            }
            #pragma unroll
            for (int u = 0; u < 4; u++)
                #pragma unroll
                for (int nn = 0; nn < 2; nn++)
                    mma_f16(oacc[u * 2 + nn], pfh[kt], &vh[u][nn * 2]);
        }
    }

    // ---- epilogue: normalize, stage O^T (reuse Q smem), fused Wproj ----
    __syncthreads();
    float* Ot = reinterpret_cast<float*>(smem);
    {
        float inv0 = 1.0f / li[0], inv1 = 1.0f / li[1];
        #pragma unroll
        for (int j = 0; j < 8; j++)
            #pragma unroll
            for (int e = 0; e < 4; e++) {
                int qrel = warp * 16 + (lane >> 2) + (e >> 1) * 8;
                int d    = j * 8 + (lane & 3) * 2 + (e & 1);
                Ot[d * OTS + qrel] = oacc[j][e] * ((e >> 1) ? inv1 : inv0);
            }
    }
    __syncthreads();

    const int tx = tid & 15;
    const int ty = tid >> 4;
    float2 r2[8][2];
    #pragma unroll
    for (int i = 0; i < 8; i++) {
        r2[i][0] = make_float2(0.f, 0.f);
        r2[i][1] = make_float2(0.f, 0.f);
    }
    #pragma unroll 4
    for (int d = 0; d < 64; d++) {
        float4 a0 = *reinterpret_cast<const float4*>(&Ot[d * OTS + ty * 8]);
        float4 a1 = *reinterpret_cast<const float4*>(&Ot[d * OTS + ty * 8 + 4]);
        float4 w  = *reinterpret_cast<const float4*>(&Wproj[d * 64 + tx * 4]);
        float2 w01 = make_float2(w.x, w.y);
        float2 w23 = make_float2(w.z, w.w);
        float a[8] = {a0.x, a0.y, a0.z, a0.w, a1.x, a1.y, a1.z, a1.w};
        #pragma unroll
        for (int i = 0; i < 8; i++) {
            float2 ad = dup2(a[i]);
            r2[i][0] = ffma2(ad, w01, r2[i][0]);
            r2[i][1] = ffma2(ad, w23, r2[i][1]);
        }
    }
    float4 bb = *reinterpret_cast<const float4*>(&bproj[tx * 4]);
    const size_t baseo = (size_t)b * T_ * H_;
    #pragma unroll
    for (int i = 0; i < 8; i++) {
        float4 ov = make_float4(r2[i][0].x + bb.x, r2[i][0].y + bb.y,
                                r2[i][1].x + bb.z, r2[i][1].y + bb.w);
        *reinterpret_cast<float4*>(
            &out[baseo + (size_t)(q0 + ty * 8 + i) * H_ + tx * 4]) = ov;
    }
}

extern "C" void kernel_launch(void* const* d_in, const int* in_sizes, int n_in,
                              void* d_out, int out_size)
{
    const float* x     = (const float*)d_in[0];
    const float* v1    = (const float*)d_in[1];
    const float* Wk    = (const float*)d_in[2];
    const float* Wq    = (const float*)d_in[3];
    const float* Wv    = (const float*)d_in[4];
    const float* Wproj = (const float*)d_in[5];
    const float* bproj = (const float*)d_in[6];
    const float* lamb  = (const float*)d_in[7];
    float* out = (float*)d_out;

    cudaFuncSetAttribute(qkv_mma_kernel,
                         cudaFuncAttributeMaxDynamicSharedMemorySize, QM_SMEM);
    cudaFuncSetAttribute(attn_tc_kernel,
                         cudaFuncAttributeMaxDynamicSharedMemorySize, AT_SMEM);

    float* v1dst = (out_size >= 2 * BT_ * H_) ? (out + (size_t)BT_ * H_) : nullptr;
    prep_kernel<<<192 + 2048, 256>>>(Wk, Wq, Wv, v1, v1dst);
    qkv_mma_kernel<<<dim3(3, BT_ / 128), 256, QM_SMEM>>>(x, v1, lamb);
    attn_tc_kernel<<<16 * B_, 256, AT_SMEM>>>(Wproj, bproj, out);
}